// round 3
// baseline (speedup 1.0000x reference)
#include <cuda_runtime.h>
#include <math.h>

// ---------------------------------------------------------------------------
// Seq2Seq LSTM: B=256, T_in=512, F=64, H=512, T_out=64
// Persistent-kernel version: 2 graph nodes total (prep + main) to avoid the
// graph-upload device allocation that a 1226-node graph triggers.
// Inner GEMM: gate-interleaved weights, packed f32x2 FMA, duplicated-A smem,
// double-buffered tiles. Grid barrier between recurrent steps.
// ---------------------------------------------------------------------------

#define Bsz   256
#define Hd    512
#define Fin   64
#define T_IN  512
#define T_OUT 64
#define N4    2048
#define BH    (Bsz*Hd)
#define NBLK  128

#define BM 64
#define BN 64
#define BK 16

// ------------------------- device scratch (static) -------------------------
__device__ float g_hseq[T_IN * BH];
__device__ float g_h1[2][BH];
__device__ float g_hd0[2][BH];
__device__ float g_hd1[2][BH];
__device__ float g_c0[BH];
__device__ float g_c1[BH];
__device__ float g_prev[Bsz];

__device__ float g_Wx0[Fin * N4];
__device__ float g_Wh0[Hd * N4];
__device__ float g_b0[N4];
__device__ float g_Wx1[Hd * N4];
__device__ float g_Wh1[Hd * N4];
__device__ float g_b1[N4];
__device__ float g_Wvd0[N4];
__device__ float g_Whd0[Hd * N4];
__device__ float g_bd0[N4];
__device__ float g_Wxd1[Hd * N4];
__device__ float g_Whd1[Hd * N4];
__device__ float g_bd1[N4];

__device__ unsigned g_cnt;
__device__ volatile unsigned g_gen;

// ------------------------------- helpers -----------------------------------
__device__ __forceinline__ void fma2(unsigned long long& d,
                                     unsigned long long a,
                                     unsigned long long b) {
    asm("fma.rn.f32x2 %0, %1, %2, %0;" : "+l"(d) : "l"(a), "l"(b));
}
__device__ __forceinline__ float2 up2(unsigned long long v) {
    float2 f;
    asm("mov.b64 {%0,%1}, %2;" : "=f"(f.x), "=f"(f.y) : "l"(v));
    return f;
}
__device__ __forceinline__ float sigf(float x) { return 1.0f / (1.0f + expf(-x)); }

__device__ __forceinline__ void grid_sync() {
    __syncthreads();
    if (threadIdx.x == 0) {
        __threadfence();
        unsigned g = g_gen;
        unsigned old = atomicAdd(&g_cnt, 1u);
        if (old == NBLK - 1) {
            g_cnt = 0;
            __threadfence();
            g_gen = g + 1;
        } else {
            while (g_gen == g) __nanosleep(64);
            __threadfence();
        }
    }
    __syncthreads();
}

// --------------------------- fused step GEMM -------------------------------
// acc += A[BM x K] * W[K x 2048] tile (A duplicated in smem for packed f32x2)
__device__ __forceinline__ void gemm_src(
    const float* __restrict__ A, int sa,
    const float* __restrict__ W, int K,
    int bm, int bn, int tid,
    float As2[2][BK][2 * BM], float Bs[2][BK][BN],
    unsigned long long acc[4][2]) {
    const int tx = tid & 15, ty = tid >> 4;
    const int arow = tid >> 2, ak = (tid & 3) << 2;
    const int bk = tid >> 4, bn4 = (tid & 15) << 2;
    const float* aptr = A + (bm + arow) * sa + ak;
    const float* bptr = W + bk * N4 + bn + bn4;
    const int ntile = K >> 4;

    float4 ar = *(const float4*)aptr;
    float4 br = *(const float4*)bptr;

    __syncthreads();   // prior users of smem are done
    {
        *(float2*)&As2[0][ak + 0][2 * arow] = make_float2(ar.x, ar.x);
        *(float2*)&As2[0][ak + 1][2 * arow] = make_float2(ar.y, ar.y);
        *(float2*)&As2[0][ak + 2][2 * arow] = make_float2(ar.z, ar.z);
        *(float2*)&As2[0][ak + 3][2 * arow] = make_float2(ar.w, ar.w);
        *(float4*)&Bs[0][bk][bn4] = br;
    }
    __syncthreads();

    int buf = 0;
    for (int t = 0; t < ntile; ++t) {
        if (t + 1 < ntile) {
            ar = *(const float4*)(aptr + (t + 1) * BK);
            br = *(const float4*)(bptr + (t + 1) * BK * N4);
        }
#pragma unroll
        for (int k = 0; k < BK; ++k) {
            ulonglong2 va = *(const ulonglong2*)&As2[buf][k][ty << 3];
            ulonglong2 vb = *(const ulonglong2*)&As2[buf][k][(ty << 3) + 4];
            ulonglong2 wb = *(const ulonglong2*)&Bs[buf][k][tx << 2];
            fma2(acc[0][0], va.x, wb.x); fma2(acc[0][1], va.x, wb.y);
            fma2(acc[1][0], va.y, wb.x); fma2(acc[1][1], va.y, wb.y);
            fma2(acc[2][0], vb.x, wb.x); fma2(acc[2][1], vb.x, wb.y);
            fma2(acc[3][0], vb.y, wb.x); fma2(acc[3][1], vb.y, wb.y);
        }
        if (t + 1 < ntile) {
            buf ^= 1;
            *(float2*)&As2[buf][ak + 0][2 * arow] = make_float2(ar.x, ar.x);
            *(float2*)&As2[buf][ak + 1][2 * arow] = make_float2(ar.y, ar.y);
            *(float2*)&As2[buf][ak + 2][2 * arow] = make_float2(ar.z, ar.z);
            *(float2*)&As2[buf][ak + 3][2 * arow] = make_float2(ar.w, ar.w);
            *(float4*)&Bs[buf][bk][bn4] = br;
            __syncthreads();
        }
    }
    __syncthreads();   // protect smem for next source
}

// LSTM pointwise epilogue: each thread owns 4 rows x 4 interleaved gate cols
__device__ __forceinline__ void lstm_pointwise(
    unsigned long long acc[4][2],
    const float* __restrict__ bias,
    const float* __restrict__ prev,
    const float* __restrict__ Wvec,
    float* __restrict__ cst,
    float* __restrict__ hnew,
    int bm, int bn, int tid) {
    const int tx = tid & 15, ty = tid >> 4;
    const int n0 = bn + (tx << 2);
    const int j = n0 >> 2;
    const float bi = bias[n0], bf = bias[n0 + 1], bg = bias[n0 + 2], bo = bias[n0 + 3];
    float wv0 = 0.f, wv1 = 0.f, wv2 = 0.f, wv3 = 0.f;
    if (Wvec) { wv0 = Wvec[n0]; wv1 = Wvec[n0 + 1]; wv2 = Wvec[n0 + 2]; wv3 = Wvec[n0 + 3]; }

#pragma unroll
    for (int r = 0; r < 4; ++r) {
        const int b = bm + (ty << 2) + r;
        float2 lo = up2(acc[r][0]);
        float2 hi = up2(acc[r][1]);
        float gi = lo.x + bi, gf = lo.y + bf, gg = hi.x + bg, go = hi.y + bo;
        if (prev) {
            float pv = prev[b];
            gi = fmaf(pv, wv0, gi); gf = fmaf(pv, wv1, gf);
            gg = fmaf(pv, wv2, gg); go = fmaf(pv, wv3, go);
        }
        const int idx = b * Hd + j;
        float cc = cst[idx];
        float cn = sigf(gf) * cc + sigf(gi) * tanhf(gg);
        float hn = sigf(go) * tanhf(cn);
        cst[idx] = cn;
        hnew[idx] = hn;
    }
}

// ------------------------------- prep kernel -------------------------------
// One launch: 5 full reorders, Wx0 reorder, Wvd0, 4 bias combines, zeros, prev
__global__ void prep_kernel(
    const float* __restrict__ x,
    const float* __restrict__ e0Wih, const float* __restrict__ e0Whh,
    const float* __restrict__ e0bih, const float* __restrict__ e0bhh,
    const float* __restrict__ e1Wih, const float* __restrict__ e1Whh,
    const float* __restrict__ e1bih, const float* __restrict__ e1bhh,
    const float* __restrict__ d0Wih, const float* __restrict__ d0Whh,
    const float* __restrict__ d0bih, const float* __restrict__ d0bhh,
    const float* __restrict__ d1Wih, const float* __restrict__ d1Whh,
    const float* __restrict__ d1bih, const float* __restrict__ d1bhh) {
    const int FULL = Hd * N4;          // 1048576
    long long idx = (long long)blockIdx.x * 256 + threadIdx.x;

    // 5 full (K=512) reorders
    if (idx < 5LL * FULL) {
        int seg = (int)(idx / FULL);
        int i = (int)(idx % FULL);
        int k = i % Hd, row = i / Hd;
        int g = row >> 9, j = row & 511;
        int dst = k * N4 + (j << 2) + g;
        const float* src; float* d;
        switch (seg) {
            case 0: src = e0Whh; d = g_Wh0;  break;
            case 1: src = e1Wih; d = g_Wx1;  break;
            case 2: src = e1Whh; d = g_Wh1;  break;
            case 3: src = d0Whh; d = g_Whd0; break;
            default: src = d1Whh; d = g_Whd1; break;
        }
        d[dst] = src[i];
        // seg 4 threads also handle d1Wih (same size)
        if (seg == 4) g_Wxd1[dst] = d1Wih[i];
        return;
    }
    idx -= 5LL * FULL;

    if (idx < Fin * N4) {              // Wx0 reorder (K=64)
        int i = (int)idx;
        int k = i % Fin, row = i / Fin;
        int g = row >> 9, j = row & 511;
        g_Wx0[k * N4 + (j << 2) + g] = e0Wih[i];
        return;
    }
    idx -= Fin * N4;

    if (idx < N4) {                    // Wvd0 (K=1) + all 4 combined biases
        int row = (int)idx;
        int g = row >> 9, j = row & 511;
        int dst = (j << 2) + g;
        g_Wvd0[dst] = d0Wih[row];
        g_b0[dst]  = e0bih[row] + e0bhh[row];
        g_b1[dst]  = e1bih[row] + e1bhh[row];
        g_bd0[dst] = d0bih[row] + d0bhh[row];
        g_bd1[dst] = d1bih[row] + d1bhh[row];
        return;
    }
    idx -= N4;

    if (idx < BH) {                    // zero c0, c1
        g_c0[idx] = 0.0f;
        g_c1[idx] = 0.0f;
        return;
    }
    idx -= BH;

    if (idx < Bsz) {                   // prev = x[:, -1, -1]
        g_prev[idx] = x[idx * T_IN * Fin + (T_IN - 1) * Fin + (Fin - 1)];
        return;
    }
    idx -= Bsz;

    if (idx == 0) { g_cnt = 0; }       // barrier state reset
}

// ------------------------------ main kernel --------------------------------
__global__ void __launch_bounds__(256, 1) main_kernel(
    const float* __restrict__ x,
    const float* __restrict__ projW,
    const float* __restrict__ projb,
    float* __restrict__ out) {
    __shared__ __align__(16) float As2[2][BK][2 * BM];
    __shared__ __align__(16) float Bs[2][BK][BN];
    __shared__ float red[8];

    const int tid = threadIdx.x;
    const int bid = blockIdx.x;
    const int bm = (bid >> 5) * BM;
    const int bn = (bid & 31) * BN;

    unsigned long long acc[4][2];

    // ---------------- encoder layer 0 ----------------
    for (int t = 0; t < T_IN; ++t) {
#pragma unroll
        for (int r = 0; r < 4; ++r) { acc[r][0] = 0ull; acc[r][1] = 0ull; }
        gemm_src(x + t * Fin, T_IN * Fin, g_Wx0, Fin, bm, bn, tid, As2, Bs, acc);
        if (t)
            gemm_src(g_hseq + (t - 1) * BH, Hd, g_Wh0, Hd, bm, bn, tid, As2, Bs, acc);
        lstm_pointwise(acc, g_b0, nullptr, nullptr, g_c0, g_hseq + t * BH, bm, bn, tid);
        grid_sync();
    }

    // ---------------- encoder layer 1 ----------------
    for (int t = 0; t < T_IN; ++t) {
#pragma unroll
        for (int r = 0; r < 4; ++r) { acc[r][0] = 0ull; acc[r][1] = 0ull; }
        gemm_src(g_hseq + t * BH, Hd, g_Wx1, Hd, bm, bn, tid, As2, Bs, acc);
        if (t)
            gemm_src(&g_h1[(t + 1) & 1][0], Hd, g_Wh1, Hd, bm, bn, tid, As2, Bs, acc);
        lstm_pointwise(acc, g_b1, nullptr, nullptr, g_c1, &g_h1[t & 1][0], bm, bn, tid);
        grid_sync();
    }

    // ---------------- decoder ----------------
    const float* h0p = g_hseq + (T_IN - 1) * BH;
    const float* h1p = &g_h1[(T_IN - 1) & 1][0];
    for (int t = 0; t < T_OUT; ++t) {
        // layer 0: K = Hd (hidden) + scalar prev handled in epilogue
#pragma unroll
        for (int r = 0; r < 4; ++r) { acc[r][0] = 0ull; acc[r][1] = 0ull; }
        gemm_src(h0p, Hd, g_Whd0, Hd, bm, bn, tid, As2, Bs, acc);
        lstm_pointwise(acc, g_bd0, g_prev, g_Wvd0, g_c0, &g_hd0[t & 1][0], bm, bn, tid);
        grid_sync();

        // layer 1
#pragma unroll
        for (int r = 0; r < 4; ++r) { acc[r][0] = 0ull; acc[r][1] = 0ull; }
        gemm_src(&g_hd0[t & 1][0], Hd, g_Wxd1, Hd, bm, bn, tid, As2, Bs, acc);
        gemm_src(h1p, Hd, g_Whd1, Hd, bm, bn, tid, As2, Bs, acc);
        lstm_pointwise(acc, g_bd1, nullptr, nullptr, g_c1, &g_hd1[t & 1][0], bm, bn, tid);
        grid_sync();

        // projection: each CTA does 2 batch rows (128 threads each)
        {
            const int b = bid * 2 + (tid >> 7);
            const int lane = tid & 127;
            const float* h = &g_hd1[t & 1][0] + b * Hd;
            float s = 0.f;
            for (int k = lane; k < Hd; k += 128) s += h[k] * projW[k];
#pragma unroll
            for (int off = 16; off > 0; off >>= 1)
                s += __shfl_xor_sync(0xffffffffu, s, off);
            if ((tid & 31) == 0) red[tid >> 5] = s;
            __syncthreads();
            if (lane == 0) {
                const int w0 = (tid >> 7) * 4;
                float v = red[w0] + red[w0 + 1] + red[w0 + 2] + red[w0 + 3] + projb[0];
                out[b * T_OUT + t] = v;
                g_prev[b] = v;
            }
        }
        grid_sync();

        h0p = &g_hd0[t & 1][0];
        h1p = &g_hd1[t & 1][0];
    }
}

// ------------------------------- host side ---------------------------------
extern "C" void kernel_launch(void* const* d_in, const int* in_sizes, int n_in,
                              void* d_out, int out_size) {
    const float* x      = (const float*)d_in[0];
    const float* e0Wih  = (const float*)d_in[2];
    const float* e0Whh  = (const float*)d_in[3];
    const float* e0bih  = (const float*)d_in[4];
    const float* e0bhh  = (const float*)d_in[5];
    const float* e1Wih  = (const float*)d_in[6];
    const float* e1Whh  = (const float*)d_in[7];
    const float* e1bih  = (const float*)d_in[8];
    const float* e1bhh  = (const float*)d_in[9];
    const float* d0Wih  = (const float*)d_in[10];
    const float* d0Whh  = (const float*)d_in[11];
    const float* d0bih  = (const float*)d_in[12];
    const float* d0bhh  = (const float*)d_in[13];
    const float* d1Wih  = (const float*)d_in[14];
    const float* d1Whh  = (const float*)d_in[15];
    const float* d1bih  = (const float*)d_in[16];
    const float* d1bhh  = (const float*)d_in[17];
    const float* projW  = (const float*)d_in[18];
    const float* projb  = (const float*)d_in[19];
    float* out = (float*)d_out;

    // prep: total work items = 5*512*2048 + 64*2048 + 2048 + 131072 + 256 + 1
    const long long total = 5LL * Hd * N4 + (long long)Fin * N4 + N4 + BH + Bsz + 1;
    const int nblk = (int)((total + 255) / 256);
    prep_kernel<<<nblk, 256>>>(x,
        e0Wih, e0Whh, e0bih, e0bhh,
        e1Wih, e1Whh, e1bih, e1bhh,
        d0Wih, d0Whh, d0bih, d0bhh,
        d1Wih, d1Whh, d1bih, d1bhh);

    main_kernel<<<NBLK, 256>>>(x, projW, projb, out);
}

// round 5
// speedup vs baseline: 2.6664x; 2.6664x over previous
#include <cuda_runtime.h>
#include <cuda_bf16.h>
#include <cstdint>
#include <math.h>

// ---------------------------------------------------------------------------
// Seq2Seq LSTM via mma.sync (HMMA bf16): B=256, T_in=512, F=64, H=512, T_out=64
// 128 persistent CTAs = 4 M-tiles(64 rows) x 32 N-tiles(64 gate-cols).
// Per step: gates = A @ W'^T with bf16 hi/lo split, 3 MMA passes (~fp32 acc).
// Register accumulators, cp.async double-buffered K-chunks of 64, ldmatrix
// with SW128 swizzle. LSTM cell state lives in registers for the whole run.
// Column remap: col = G*32 + g*8 + u (G=unit-group, u=unit in group, g=gate)
// so each thread's D fragment holds all 4 gates of its units.
// ---------------------------------------------------------------------------

using bf16 = __nv_bfloat16;

#define Bsz   256
#define Hd    512
#define Fin   64
#define T_IN  512
#define T_OUT 64
#define N4    2048
#define BH    (Bsz*Hd)
#define NBLK  128
#define THR   256

// smem buffer layout (per stage): A_hi 8K | A_lo 8K | B_hi 8K | B_lo 8K
#define OFF_AL 8192
#define OFF_BH 16384
#define OFF_BL 24576
#define BUFB   32768
#define DSMEM  (2*BUFB + 1024)

// ------------------------- device scratch (static) -------------------------
__device__ __align__(16) bf16 g_xch[(size_t)T_IN * Bsz * Fin];
__device__ __align__(16) bf16 g_xcl[(size_t)T_IN * Bsz * Fin];
__device__ __align__(16) bf16 g_hsh[(size_t)T_IN * BH];
__device__ __align__(16) bf16 g_hsl[(size_t)T_IN * BH];
__device__ __align__(16) bf16 g_h1h[2][BH], g_h1l[2][BH];
__device__ __align__(16) bf16 g_d0h[2][BH], g_d0l[2][BH];
__device__ __align__(16) bf16 g_d1h[2][BH], g_d1l[2][BH];
__device__ float g_prev[Bsz];

// weights, remapped rows: row' = (j>>3)*32 + g*8 + (j&7), layout [2048][K]
__device__ __align__(16) bf16 gB_x0h[N4 * Fin], gB_x0l[N4 * Fin];
__device__ __align__(16) bf16 gB_h0h[N4 * Hd],  gB_h0l[N4 * Hd];
__device__ __align__(16) bf16 gB_x1h[N4 * Hd],  gB_x1l[N4 * Hd];
__device__ __align__(16) bf16 gB_h1h[N4 * Hd],  gB_h1l[N4 * Hd];
__device__ __align__(16) bf16 gB_d0h[N4 * Hd],  gB_d0l[N4 * Hd];
__device__ __align__(16) bf16 gB_x1dh[N4 * Hd], gB_x1dl[N4 * Hd];
__device__ __align__(16) bf16 gB_d1h[N4 * Hd],  gB_d1l[N4 * Hd];

__device__ __align__(16) float g_b0[N4], g_b1[N4], g_bd0[N4], g_bd1[N4], g_Wv[N4];

__device__ unsigned g_cnt;
__device__ volatile unsigned g_gen;

// ------------------------------- asm helpers -------------------------------
#define LDSM4(R, A) \
    asm volatile("ldmatrix.sync.aligned.m8n8.x4.shared.b16 {%0,%1,%2,%3}, [%4];" \
        : "=r"((R)[0]), "=r"((R)[1]), "=r"((R)[2]), "=r"((R)[3]) : "r"(A))

#define MMA(D, A, B) \
    asm volatile("mma.sync.aligned.m16n8k16.row.col.f32.bf16.bf16.f32 " \
        "{%0,%1,%2,%3}, {%4,%5,%6,%7}, {%8,%9}, {%0,%1,%2,%3};" \
        : "+f"((D)[0]), "+f"((D)[1]), "+f"((D)[2]), "+f"((D)[3]) \
        : "r"((A)[0]), "r"((A)[1]), "r"((A)[2]), "r"((A)[3]), \
          "r"((B)[0]), "r"((B)[1]))

#define CP16(sa, ga) \
    asm volatile("cp.async.cg.shared.global [%0], [%1], 16;" :: "r"(sa), "l"(ga))
#define CP_COMMIT() asm volatile("cp.async.commit_group;")
#define CP_WAIT0()  asm volatile("cp.async.wait_group 0;" ::: "memory")
#define CP_WAIT1()  asm volatile("cp.async.wait_group 1;" ::: "memory")

__device__ __forceinline__ uint32_t smem_u32(const void* p) {
    uint32_t a;
    asm("{ .reg .u64 t; cvta.to.shared.u64 t, %1; cvt.u32.u64 %0, t; }"
        : "=r"(a) : "l"(p));
    return a;
}
__device__ __forceinline__ float sigf(float x) { return 1.0f / (1.0f + expf(-x)); }

__device__ __forceinline__ void grid_sync() {
    __syncthreads();
    if (threadIdx.x == 0) {
        __threadfence();
        unsigned g = g_gen;
        unsigned old = atomicAdd(&g_cnt, 1u);
        if (old == NBLK - 1) {
            g_cnt = 0;
            __threadfence();
            g_gen = g + 1;
        } else {
            while (g_gen == g) __nanosleep(64);
            __threadfence();
        }
    }
    __syncthreads();
}

// ----------------------------- GEMM machinery ------------------------------
struct Src {
    const bf16 *Ah, *Al; int as;       // A [row][as], row = batch index
    const bf16 *Bh, *Bl;               // B' [2048][K], K = nch*64
    int nch;
};

// Load one K=64 chunk: A 64rows x 64k hi/lo, B 64rows x 64k hi/lo via cp.async
__device__ __forceinline__ void issue_chunk(uint32_t dsm32, int buf,
                                            const Src* s, int nsrc, int c,
                                            int bm, int colb, int tid) {
    const Src* sp = (nsrc > 1 && c >= s[0].nch) ? &s[1] : &s[0];
    const int ck = (sp == &s[1]) ? c - s[0].nch : c;
    const uint32_t base = dsm32 + buf * BUFB;
    const int K = sp->nch * 64;
#pragma unroll
    for (int i = 0; i < 2; ++i) {
        const int uu = tid * 2 + i;
        const int row = uu >> 3, seg = uu & 7;
        const int off = uu * 16;
        const int sw = off ^ ((off >> 3) & 0x70);
        // A
        const bf16* gah = sp->Ah + (size_t)(bm + row) * sp->as + ck * 64 + seg * 8;
        const bf16* gal = sp->Al + (size_t)(bm + row) * sp->as + ck * 64 + seg * 8;
        CP16(base + sw, gah);
        CP16(base + OFF_AL + sw, gal);
        // B
        const bf16* gbh = sp->Bh + (size_t)(colb + row) * K + ck * 64 + seg * 8;
        const bf16* gbl = sp->Bl + (size_t)(colb + row) * K + ck * 64 + seg * 8;
        CP16(base + OFF_BH + sw, gbh);
        CP16(base + OFF_BL + sw, gbl);
    }
}

__device__ __forceinline__ void compute_chunk(uint32_t sbase, float acc[4][4],
                                              int lane, int wm, int wn) {
    const uint32_t sA  = sbase;
    const uint32_t sAl = sbase + OFF_AL;
    const uint32_t sB  = sbase + OFF_BH;
    const uint32_t sBl = sbase + OFF_BL;
    const int abase = (wm * 16 + (lane & 15)) * 128 + ((lane >> 4) << 4);
    const int bbase0 = (wn * 32 + (lane & 7) + ((lane >> 4) << 3)) * 128
                     + (((lane >> 3) & 1) << 4);
#pragma unroll
    for (int ka = 0; ka < 4; ++ka) {
        uint32_t ah[4], al[4], bh[8], bl[8];
        const int ao = abase + ka * 32;
        const int asw = ao ^ ((ao >> 3) & 0x70);
        LDSM4(ah, sA + asw);
        LDSM4(al, sAl + asw);
        const int bo0 = bbase0 + ka * 32;
        const int bo1 = bo0 + 16 * 128;
        const int bsw0 = bo0 ^ ((bo0 >> 3) & 0x70);
        const int bsw1 = bo1 ^ ((bo1 >> 3) & 0x70);
        LDSM4(bh, sB + bsw0);
        LDSM4(bh + 4, sB + bsw1);
        LDSM4(bl, sBl + bsw0);
        LDSM4(bl + 4, sBl + bsw1);
#pragma unroll
        for (int a = 0; a < 4; ++a) {
            MMA(acc[a], ah, bh + 2 * a);
            MMA(acc[a], ah, bl + 2 * a);
            MMA(acc[a], al, bh + 2 * a);
        }
    }
}

__device__ __forceinline__ void step_gemm(uint32_t dsm32, const Src* s, int nsrc,
                                          float acc[4][4], int bm, int colb,
                                          int tid, int lane, int wm, int wn) {
#pragma unroll
    for (int a = 0; a < 4; ++a)
#pragma unroll
        for (int d = 0; d < 4; ++d) acc[a][d] = 0.0f;

    const int n = s[0].nch + (nsrc > 1 ? s[1].nch : 0);
    issue_chunk(dsm32, 0, s, nsrc, 0, bm, colb, tid);
    CP_COMMIT();
    for (int c = 0; c < n; ++c) {
        if (c + 1 < n) {
            issue_chunk(dsm32, (c + 1) & 1, s, nsrc, c + 1, bm, colb, tid);
            CP_COMMIT();
            CP_WAIT1();
        } else {
            CP_WAIT0();
        }
        __syncthreads();
        compute_chunk(dsm32 + (c & 1) * BUFB, acc, lane, wm, wn);
        __syncthreads();
    }
}

// LSTM pointwise epilogue: thread owns rows {m, m+8} x units {u0, u0+1},
// all 4 gates each (acc[g][rr*2+p]).
__device__ __forceinline__ void epilogue_lstm(float acc[4][4], float* c,
                                              const float* bias,
                                              const float* prevv, const float* Wv,
                                              bf16* Hh, bf16* Hl,
                                              int bm, int G, int wm,
                                              int lane) {
    const int q = lane & 3, r = lane >> 2;
    const float2* b2 = (const float2*)bias;
    float2 bb[4];
#pragma unroll
    for (int g = 0; g < 4; ++g) bb[g] = b2[G * 16 + g * 4 + q];
    float2 wv[4];
    if (Wv) {
        const float2* w2 = (const float2*)Wv;
#pragma unroll
        for (int g = 0; g < 4; ++g) wv[g] = w2[G * 16 + g * 4 + q];
    }
#pragma unroll
    for (int rr = 0; rr < 2; ++rr) {
        const int m = bm + wm * 16 + r + rr * 8;
        float pv = 0.0f;
        if (prevv) pv = prevv[m];
        uint32_t ph, pl;
#pragma unroll
        for (int p = 0; p < 2; ++p) {
            const int d = rr * 2 + p;
            float gi = acc[0][d] + (p ? bb[0].y : bb[0].x);
            float gf = acc[1][d] + (p ? bb[1].y : bb[1].x);
            float gg = acc[2][d] + (p ? bb[2].y : bb[2].x);
            float go = acc[3][d] + (p ? bb[3].y : bb[3].x);
            if (Wv) {
                gi = fmaf(pv, p ? wv[0].y : wv[0].x, gi);
                gf = fmaf(pv, p ? wv[1].y : wv[1].x, gf);
                gg = fmaf(pv, p ? wv[2].y : wv[2].x, gg);
                go = fmaf(pv, p ? wv[3].y : wv[3].x, go);
            }
            float cn = sigf(gf) * c[d] + sigf(gi) * tanhf(gg);
            float hn = sigf(go) * tanhf(cn);
            c[d] = cn;
            bf16 hh = __float2bfloat16(hn);
            bf16 hl = __float2bfloat16(hn - __bfloat162float(hh));
            uint32_t uh = (uint32_t)__bfloat16_as_ushort(hh) << (p * 16);
            uint32_t ul = (uint32_t)__bfloat16_as_ushort(hl) << (p * 16);
            if (p == 0) { ph = uh; pl = ul; }
            else        { ph |= uh; pl |= ul; }
        }
        const size_t hb = (size_t)m * Hd + G * 8 + 2 * q;
        *(uint32_t*)(Hh + hb) = ph;
        *(uint32_t*)(Hl + hb) = pl;
    }
}

// ------------------------------- prep kernel -------------------------------
__device__ __forceinline__ void split_store(float v, bf16* h, bf16* l, size_t i) {
    bf16 hi = __float2bfloat16(v);
    h[i] = hi;
    l[i] = __float2bfloat16(v - __bfloat162float(hi));
}
__device__ __forceinline__ int remap_row(int r) {
    const int g = r >> 9, j = r & 511;
    return ((j >> 3) << 5) + (g << 3) + (j & 7);
}

__global__ void prep_kernel(
    const float* __restrict__ x,
    const float* __restrict__ e0Wih, const float* __restrict__ e0Whh,
    const float* __restrict__ e0bih, const float* __restrict__ e0bhh,
    const float* __restrict__ e1Wih, const float* __restrict__ e1Whh,
    const float* __restrict__ e1bih, const float* __restrict__ e1bhh,
    const float* __restrict__ d0Wih, const float* __restrict__ d0Whh,
    const float* __restrict__ d0bih, const float* __restrict__ d0bhh,
    const float* __restrict__ d1Wih, const float* __restrict__ d1Whh,
    const float* __restrict__ d1bih, const float* __restrict__ d1bhh) {
    const size_t FULL = (size_t)N4 * Hd;
    long long idx = (long long)blockIdx.x * 256 + threadIdx.x;

    if (idx < (long long)(6 * FULL)) {
        int seg = (int)(idx / FULL);
        size_t i = (size_t)(idx % FULL);
        int r = (int)(i / Hd), k = (int)(i % Hd);
        size_t dst = (size_t)remap_row(r) * Hd + k;
        const float* src; bf16* dh; bf16* dl;
        switch (seg) {
            case 0: src = e0Whh; dh = gB_h0h;  dl = gB_h0l;  break;
            case 1: src = e1Wih; dh = gB_x1h;  dl = gB_x1l;  break;
            case 2: src = e1Whh; dh = gB_h1h;  dl = gB_h1l;  break;
            case 3: src = d0Whh; dh = gB_d0h;  dl = gB_d0l;  break;
            case 4: src = d1Wih; dh = gB_x1dh; dl = gB_x1dl; break;
            default: src = d1Whh; dh = gB_d1h; dl = gB_d1l;  break;
        }
        split_store(src[i], dh, dl, dst);
        return;
    }
    idx -= 6LL * FULL;

    if (idx < (long long)N4 * Fin) {   // Wx0
        size_t i = (size_t)idx;
        int r = (int)(i / Fin), k = (int)(i % Fin);
        split_store(e0Wih[i], gB_x0h, gB_x0l, (size_t)remap_row(r) * Fin + k);
        return;
    }
    idx -= (long long)N4 * Fin;

    if (idx < (long long)Bsz * T_IN * Fin) {   // x -> [t][b][f] hi/lo
        size_t i = (size_t)idx;
        int b = (int)(i / (T_IN * Fin));
        int t = (int)((i / Fin) % T_IN);
        int f = (int)(i % Fin);
        split_store(x[i], g_xch, g_xcl, (size_t)t * Bsz * Fin + b * Fin + f);
        return;
    }
    idx -= (long long)Bsz * T_IN * Fin;

    if (idx < N4) {                    // biases + Wv, remapped
        int r = (int)idx;
        int dst = remap_row(r);
        g_Wv[dst]  = d0Wih[r];
        g_b0[dst]  = e0bih[r] + e0bhh[r];
        g_b1[dst]  = e1bih[r] + e1bhh[r];
        g_bd0[dst] = d0bih[r] + d0bhh[r];
        g_bd1[dst] = d1bih[r] + d1bhh[r];
        return;
    }
    idx -= N4;

    if (idx < Bsz) {
        g_prev[idx] = x[(size_t)(idx + 1) * T_IN * Fin - 1];
        return;
    }
    idx -= Bsz;
    if (idx == 0) g_cnt = 0;
}

// ------------------------------ main kernel --------------------------------
__global__ void __launch_bounds__(THR, 1)
main_kernel(const float* __restrict__ projW,
            const float* __restrict__ projb,
            float* __restrict__ out) {
    extern __shared__ char dsm_raw[];
    const uint32_t raw32 = smem_u32(dsm_raw);
    const uint32_t dsm32 = (raw32 + 1023u) & ~1023u;

    const int tid  = threadIdx.x;
    const int lane = tid & 31;
    const int w    = tid >> 5;         // 0..7
    const int wm   = w & 3;            // M sub-slice (16 rows)
    const int wn   = w >> 2;           // N half (32 cols)
    const int bid  = blockIdx.x;       // 128 CTAs: 4 M x 32 N
    const int mT   = bid >> 5;         // 0..3
    const int nT   = bid & 31;         // 0..31
    const int bm   = mT * 64;
    const int colb = nT * 64;
    const int G    = nT * 2 + wn;      // unit group (8 units)

    float acc[4][4];
    float c0[4], c1[4];
#pragma unroll
    for (int d = 0; d < 4; ++d) { c0[d] = 0.0f; c1[d] = 0.0f; }

    Src s[2];

    // ---------------- encoder layer 0 ----------------
    for (int t = 0; t < T_IN; ++t) {
        s[0] = { g_xch + (size_t)t * Bsz * Fin, g_xcl + (size_t)t * Bsz * Fin, Fin,
                 gB_x0h, gB_x0l, 1 };
        s[1] = { g_hsh + (size_t)(t - 1) * BH, g_hsl + (size_t)(t - 1) * BH, Hd,
                 gB_h0h, gB_h0l, 8 };
        step_gemm(dsm32, s, t ? 2 : 1, acc, bm, colb, tid, lane, wm, wn);
        epilogue_lstm(acc, c0, g_b0, nullptr, nullptr,
                      g_hsh + (size_t)t * BH, g_hsl + (size_t)t * BH,
                      bm, G, wm, lane);
        grid_sync();
    }

    // ---------------- encoder layer 1 ----------------
    for (int t = 0; t < T_IN; ++t) {
        s[0] = { g_hsh + (size_t)t * BH, g_hsl + (size_t)t * BH, Hd,
                 gB_x1h, gB_x1l, 8 };
        s[1] = { &g_h1h[(t + 1) & 1][0], &g_h1l[(t + 1) & 1][0], Hd,
                 gB_h1h, gB_h1l, 8 };
        step_gemm(dsm32, s, t ? 2 : 1, acc, bm, colb, tid, lane, wm, wn);
        epilogue_lstm(acc, c1, g_b1, nullptr, nullptr,
                      &g_h1h[t & 1][0], &g_h1l[t & 1][0], bm, G, wm, lane);
        grid_sync();
    }

    // ---------------- decoder ----------------
    const bf16 *h0h = g_hsh + (size_t)(T_IN - 1) * BH;
    const bf16 *h0l = g_hsl + (size_t)(T_IN - 1) * BH;
    const bf16 *h1h = &g_h1h[(T_IN - 1) & 1][0];
    const bf16 *h1l = &g_h1l[(T_IN - 1) & 1][0];

    for (int t = 0; t < T_OUT; ++t) {
        s[0] = { h0h, h0l, Hd, gB_d0h, gB_d0l, 8 };
        step_gemm(dsm32, s, 1, acc, bm, colb, tid, lane, wm, wn);
        epilogue_lstm(acc, c0, g_bd0, g_prev, g_Wv,
                      &g_d0h[t & 1][0], &g_d0l[t & 1][0], bm, G, wm, lane);
        grid_sync();

        s[0] = { &g_d0h[t & 1][0], &g_d0l[t & 1][0], Hd, gB_x1dh, gB_x1dl, 8 };
        s[1] = { h1h, h1l, Hd, gB_d1h, gB_d1l, 8 };
        step_gemm(dsm32, s, 2, acc, bm, colb, tid, lane, wm, wn);
        epilogue_lstm(acc, c1, g_bd1, nullptr, nullptr,
                      &g_d1h[t & 1][0], &g_d1l[t & 1][0], bm, G, wm, lane);
        grid_sync();

        // projection: 2 batch rows per CTA (warps 0 and 1)
        if (w < 2) {
            const int b = bid * 2 + w;
            const bf16* hh = &g_d1h[t & 1][(size_t)b * Hd];
            const bf16* hl = &g_d1l[t & 1][(size_t)b * Hd];
            float sum = 0.0f;
            for (int k = lane; k < Hd; k += 32)
                sum += (__bfloat162float(hh[k]) + __bfloat162float(hl[k])) * projW[k];
#pragma unroll
            for (int off = 16; off > 0; off >>= 1)
                sum += __shfl_xor_sync(0xffffffffu, sum, off);
            if (lane == 0) {
                float v = sum + projb[0];
                out[(size_t)b * T_OUT + t] = v;
                g_prev[b] = v;
            }
        }
        grid_sync();

        h0h = &g_d0h[t & 1][0]; h0l = &g_d0l[t & 1][0];
        h1h = &g_d1h[t & 1][0]; h1l = &g_d1l[t & 1][0];
    }
}

// ------------------------------- host side ---------------------------------
extern "C" void kernel_launch(void* const* d_in, const int* in_sizes, int n_in,
                              void* d_out, int out_size) {
    const float* x      = (const float*)d_in[0];
    const float* e0Wih  = (const float*)d_in[2];
    const float* e0Whh  = (const float*)d_in[3];
    const float* e0bih  = (const float*)d_in[4];
    const float* e0bhh  = (const float*)d_in[5];
    const float* e1Wih  = (const float*)d_in[6];
    const float* e1Whh  = (const float*)d_in[7];
    const float* e1bih  = (const float*)d_in[8];
    const float* e1bhh  = (const float*)d_in[9];
    const float* d0Wih  = (const float*)d_in[10];
    const float* d0Whh  = (const float*)d_in[11];
    const float* d0bih  = (const float*)d_in[12];
    const float* d0bhh  = (const float*)d_in[13];
    const float* d1Wih  = (const float*)d_in[14];
    const float* d1Whh  = (const float*)d_in[15];
    const float* d1bih  = (const float*)d_in[16];
    const float* d1bhh  = (const float*)d_in[17];
    const float* projW  = (const float*)d_in[18];
    const float* projb  = (const float*)d_in[19];
    float* out = (float*)d_out;

    const long long total = 6LL * N4 * Hd + (long long)N4 * Fin
                          + (long long)Bsz * T_IN * Fin + N4 + Bsz + 1;
    const int nblk = (int)((total + 255) / 256);
    prep_kernel<<<nblk, 256>>>(x,
        e0Wih, e0Whh, e0bih, e0bhh,
        e1Wih, e1Whh, e1bih, e1bhh,
        d0Wih, d0Whh, d0bih, d0bhh,
        d1Wih, d1Whh, d1bih, d1bhh);

    cudaFuncSetAttribute(main_kernel, cudaFuncAttributeMaxDynamicSharedMemorySize, DSMEM);
    main_kernel<<<NBLK, THR, DSMEM>>>(projW, projb, out);
}

// round 6
// speedup vs baseline: 2.7347x; 1.0256x over previous
#include <cuda_runtime.h>
#include <cuda_bf16.h>
#include <cstdint>
#include <math.h>

// ---------------------------------------------------------------------------
// Seq2Seq LSTM via mma.sync (HMMA bf16): B=256, T_in=512, F=64, H=512, T_out=64
// Round 6: 4-stage cp.async ring (1 syncthreads/chunk), encoder wavefront
// fusion (enc0 t + enc1 t-1 per grid sync), projection fused into dec1
// epilogue via atomicAdd ping-pong. 128 persistent CTAs (4M x 32N tiles).
// ---------------------------------------------------------------------------

using bf16 = __nv_bfloat16;

#define Bsz   256
#define Hd    512
#define Fin   64
#define T_IN  512
#define T_OUT 64
#define N4    2048
#define BH    (Bsz*Hd)
#define NBLK  128
#define THR   256

// per-stage smem: A_hi 8K | A_lo 8K | B_hi 8K | B_lo 8K
#define OFF_AL 8192
#define OFF_BH 16384
#define OFF_BL 24576
#define BUFB   32768
#define NSTAGE 4
#define DSMEM  (NSTAGE*BUFB + 1024)

// ------------------------- device scratch (static) -------------------------
__device__ __align__(16) bf16 g_xch[(size_t)T_IN * Bsz * Fin];
__device__ __align__(16) bf16 g_xcl[(size_t)T_IN * Bsz * Fin];
__device__ __align__(16) bf16 g_hsh[(size_t)T_IN * BH];
__device__ __align__(16) bf16 g_hsl[(size_t)T_IN * BH];
__device__ __align__(16) bf16 g_h1h[2][BH], g_h1l[2][BH];
__device__ __align__(16) bf16 g_d0h[2][BH], g_d0l[2][BH];
__device__ __align__(16) bf16 g_d1h[2][BH], g_d1l[2][BH];
__device__ float g_pacc[2][Bsz];          // proj ping-pong accumulators

// weights, remapped rows: row' = (j>>3)*32 + g*8 + (j&7), layout [2048][K]
__device__ __align__(16) bf16 gB_x0h[N4 * Fin], gB_x0l[N4 * Fin];
__device__ __align__(16) bf16 gB_h0h[N4 * Hd],  gB_h0l[N4 * Hd];
__device__ __align__(16) bf16 gB_x1h[N4 * Hd],  gB_x1l[N4 * Hd];
__device__ __align__(16) bf16 gB_h1h[N4 * Hd],  gB_h1l[N4 * Hd];
__device__ __align__(16) bf16 gB_d0h[N4 * Hd],  gB_d0l[N4 * Hd];
__device__ __align__(16) bf16 gB_x1dh[N4 * Hd], gB_x1dl[N4 * Hd];
__device__ __align__(16) bf16 gB_d1h[N4 * Hd],  gB_d1l[N4 * Hd];

__device__ __align__(16) float g_b0[N4], g_b1[N4], g_bd0[N4], g_bd1[N4], g_Wv[N4];

__device__ unsigned g_cnt;
__device__ volatile unsigned g_gen;

// ------------------------------- asm helpers -------------------------------
#define LDSM4(R, A) \
    asm volatile("ldmatrix.sync.aligned.m8n8.x4.shared.b16 {%0,%1,%2,%3}, [%4];" \
        : "=r"((R)[0]), "=r"((R)[1]), "=r"((R)[2]), "=r"((R)[3]) : "r"(A))

#define MMA(D, A, B) \
    asm volatile("mma.sync.aligned.m16n8k16.row.col.f32.bf16.bf16.f32 " \
        "{%0,%1,%2,%3}, {%4,%5,%6,%7}, {%8,%9}, {%0,%1,%2,%3};" \
        : "+f"((D)[0]), "+f"((D)[1]), "+f"((D)[2]), "+f"((D)[3]) \
        : "r"((A)[0]), "r"((A)[1]), "r"((A)[2]), "r"((A)[3]), \
          "r"((B)[0]), "r"((B)[1]))

#define CP16(sa, ga) \
    asm volatile("cp.async.cg.shared.global [%0], [%1], 16;" :: "r"(sa), "l"(ga))
#define CP_COMMIT() asm volatile("cp.async.commit_group;")
#define CP_WAIT0()  asm volatile("cp.async.wait_group 0;" ::: "memory")
#define CP_WAIT1()  asm volatile("cp.async.wait_group 1;" ::: "memory")
#define CP_WAIT2()  asm volatile("cp.async.wait_group 2;" ::: "memory")

__device__ __forceinline__ uint32_t smem_u32(const void* p) {
    uint32_t a;
    asm("{ .reg .u64 t; cvta.to.shared.u64 t, %1; cvt.u32.u64 %0, t; }"
        : "=r"(a) : "l"(p));
    return a;
}
__device__ __forceinline__ float sigf(float x) { return 1.0f / (1.0f + expf(-x)); }

__device__ __forceinline__ void grid_sync() {
    __syncthreads();
    if (threadIdx.x == 0) {
        __threadfence();
        unsigned g = g_gen;
        unsigned old = atomicAdd(&g_cnt, 1u);
        if (old == NBLK - 1) {
            g_cnt = 0;
            __threadfence();
            g_gen = g + 1;
        } else {
            while (g_gen == g) __nanosleep(64);
            __threadfence();
        }
    }
    __syncthreads();
}

// ----------------------------- GEMM machinery ------------------------------
struct Seg {
    const bf16 *Ah, *Al;   // A [row][K]
    const bf16 *Bh, *Bl;   // B' [2048][K]
    int K;                 // 64 or 512 (A stride == B stride == K here)
};

// Issue one K=64 chunk into ring stage (c & 3) via cp.async
__device__ __forceinline__ void issue_chunk(uint32_t dsm32, const Seg* segs,
                                            int c, int bm, int colb, int tid) {
    int ck = c, si = 0;
    int n = segs[0].K >> 6;
    while (ck >= n) { ck -= n; ++si; n = segs[si].K >> 6; }
    const Seg sp = segs[si];
    const uint32_t base = dsm32 + (c & (NSTAGE - 1)) * BUFB;
    const int K = sp.K;
#pragma unroll
    for (int i = 0; i < 2; ++i) {
        const int uu = tid * 2 + i;
        const int row = uu >> 3, seg = uu & 7;
        const int off = uu * 16;
        const int sw = off ^ ((off >> 3) & 0x70);
        const bf16* gah = sp.Ah + (size_t)(bm + row) * K + ck * 64 + seg * 8;
        const bf16* gal = sp.Al + (size_t)(bm + row) * K + ck * 64 + seg * 8;
        CP16(base + sw, gah);
        CP16(base + OFF_AL + sw, gal);
        const bf16* gbh = sp.Bh + (size_t)(colb + row) * K + ck * 64 + seg * 8;
        const bf16* gbl = sp.Bl + (size_t)(colb + row) * K + ck * 64 + seg * 8;
        CP16(base + OFF_BH + sw, gbh);
        CP16(base + OFF_BL + sw, gbl);
    }
}

__device__ __forceinline__ void compute_chunk(uint32_t sbase, float acc[4][4],
                                              int lane, int wm, int wn) {
    const uint32_t sA  = sbase;
    const uint32_t sAl = sbase + OFF_AL;
    const uint32_t sB  = sbase + OFF_BH;
    const uint32_t sBl = sbase + OFF_BL;
    const int abase = (wm * 16 + (lane & 15)) * 128 + ((lane >> 4) << 4);
    const int bbase0 = (wn * 32 + (lane & 7) + ((lane >> 4) << 3)) * 128
                     + (((lane >> 3) & 1) << 4);
#pragma unroll
    for (int ka = 0; ka < 4; ++ka) {
        uint32_t ah[4], al[4], bh[8], bl[8];
        const int ao = abase + ka * 32;
        const int asw = ao ^ ((ao >> 3) & 0x70);
        LDSM4(ah, sA + asw);
        LDSM4(al, sAl + asw);
        const int bo0 = bbase0 + ka * 32;
        const int bo1 = bo0 + 16 * 128;
        const int bsw0 = bo0 ^ ((bo0 >> 3) & 0x70);
        const int bsw1 = bo1 ^ ((bo1 >> 3) & 0x70);
        LDSM4(bh, sB + bsw0);
        LDSM4(bh + 4, sB + bsw1);
        LDSM4(bl, sBl + bsw0);
        LDSM4(bl + 4, sBl + bsw1);
#pragma unroll
        for (int a = 0; a < 4; ++a) {
            MMA(acc[a], ah, bh + 2 * a);
            MMA(acc[a], ah, bl + 2 * a);
            MMA(acc[a], al, bh + 2 * a);
        }
    }
}

// 4-stage pipelined GEMM over concatenated segments; chunks < split -> accA,
// else accB. One __syncthreads per chunk; correct tail waits.
__device__ __forceinline__ void pipe_gemm(uint32_t dsm32, const Seg* segs, int nseg,
                                          int split, float accA[4][4], float accB[4][4],
                                          int bm, int colb, int tid, int lane,
                                          int wm, int wn) {
    int tot = 0;
    for (int i = 0; i < nseg; ++i) tot += segs[i].K >> 6;
    const int pre = tot < NSTAGE - 1 ? tot : NSTAGE - 1;
    for (int c = 0; c < pre; ++c) {
        issue_chunk(dsm32, segs, c, bm, colb, tid);
        CP_COMMIT();
    }
    for (int c = 0; c < tot; ++c) {
        if (c + 3 <= tot) CP_WAIT2();        // chunk c landed (general case)
        else if (c + 2 == tot) CP_WAIT1();   // second-to-last
        else CP_WAIT0();                     // last
        __syncthreads();
        if (c + 3 < tot) {
            issue_chunk(dsm32, segs, c + 3, bm, colb, tid);
            CP_COMMIT();
        }
        const uint32_t sbase = dsm32 + (c & (NSTAGE - 1)) * BUFB;
        if (c < split) compute_chunk(sbase, accA, lane, wm, wn);
        else           compute_chunk(sbase, accB, lane, wm, wn);
    }
}

#define ZERO_ACC(A) \
    do { _Pragma("unroll") for (int _a = 0; _a < 4; ++_a) \
         _Pragma("unroll") for (int _d = 0; _d < 4; ++_d) (A)[_a][_d] = 0.0f; } while (0)

// LSTM pointwise epilogue: thread owns rows {m, m+8} x units {u0,u0+1} for all
// 4 gates. Optionally fuses the projection partial-dot (atomicAdd into pacc).
__device__ __forceinline__ void epilogue_lstm(float acc[4][4], float* c,
                                              const float* bias,
                                              const float* prevv, const float* Wv,
                                              bf16* Hh, bf16* Hl,
                                              const float* pjW, float* pacc,
                                              int bm, int G, int wm, int lane) {
    const int q = lane & 3, r = lane >> 2;
    const float2* b2 = (const float2*)bias;
    float2 bb[4];
#pragma unroll
    for (int g = 0; g < 4; ++g) bb[g] = b2[G * 16 + g * 4 + q];
    float2 wv[4];
    if (Wv) {
        const float2* w2 = (const float2*)Wv;
#pragma unroll
        for (int g = 0; g < 4; ++g) wv[g] = w2[G * 16 + g * 4 + q];
    }
    float rsum[2] = {0.0f, 0.0f};
#pragma unroll
    for (int rr = 0; rr < 2; ++rr) {
        const int m = bm + wm * 16 + r + rr * 8;
        float pv = 0.0f;
        if (prevv) pv = prevv[m];
        uint32_t ph, pl;
#pragma unroll
        for (int p = 0; p < 2; ++p) {
            const int d = rr * 2 + p;
            float gi = acc[0][d] + (p ? bb[0].y : bb[0].x);
            float gf = acc[1][d] + (p ? bb[1].y : bb[1].x);
            float gg = acc[2][d] + (p ? bb[2].y : bb[2].x);
            float go = acc[3][d] + (p ? bb[3].y : bb[3].x);
            if (Wv) {
                gi = fmaf(pv, p ? wv[0].y : wv[0].x, gi);
                gf = fmaf(pv, p ? wv[1].y : wv[1].x, gf);
                gg = fmaf(pv, p ? wv[2].y : wv[2].x, gg);
                go = fmaf(pv, p ? wv[3].y : wv[3].x, go);
            }
            float cn = sigf(gf) * c[d] + sigf(gi) * tanhf(gg);
            float hn = sigf(go) * tanhf(cn);
            c[d] = cn;
            if (pjW) rsum[rr] = fmaf(hn, pjW[G * 8 + 2 * q + p], rsum[rr]);
            bf16 hh = __float2bfloat16(hn);
            bf16 hl = __float2bfloat16(hn - __bfloat162float(hh));
            uint32_t uh = (uint32_t)__bfloat16_as_ushort(hh) << (p * 16);
            uint32_t ul = (uint32_t)__bfloat16_as_ushort(hl) << (p * 16);
            if (p == 0) { ph = uh; pl = ul; }
            else        { ph |= uh; pl |= ul; }
        }
        const size_t hb = (size_t)m * Hd + G * 8 + 2 * q;
        *(uint32_t*)(Hh + hb) = ph;
        *(uint32_t*)(Hl + hb) = pl;
    }
    if (pjW) {
#pragma unroll
        for (int rr = 0; rr < 2; ++rr) {
            rsum[rr] += __shfl_xor_sync(0xffffffffu, rsum[rr], 1);
            rsum[rr] += __shfl_xor_sync(0xffffffffu, rsum[rr], 2);
        }
        if (q == 0) {
            atomicAdd(&pacc[bm + wm * 16 + r], rsum[0]);
            atomicAdd(&pacc[bm + wm * 16 + r + 8], rsum[1]);
        }
    }
}

// ------------------------------- prep kernel -------------------------------
__device__ __forceinline__ void split_store(float v, bf16* h, bf16* l, size_t i) {
    bf16 hi = __float2bfloat16(v);
    h[i] = hi;
    l[i] = __float2bfloat16(v - __bfloat162float(hi));
}
__device__ __forceinline__ int remap_row(int r) {
    const int g = r >> 9, j = r & 511;
    return ((j >> 3) << 5) + (g << 3) + (j & 7);
}

__global__ void prep_kernel(
    const float* __restrict__ x,
    const float* __restrict__ e0Wih, const float* __restrict__ e0Whh,
    const float* __restrict__ e0bih, const float* __restrict__ e0bhh,
    const float* __restrict__ e1Wih, const float* __restrict__ e1Whh,
    const float* __restrict__ e1bih, const float* __restrict__ e1bhh,
    const float* __restrict__ d0Wih, const float* __restrict__ d0Whh,
    const float* __restrict__ d0bih, const float* __restrict__ d0bhh,
    const float* __restrict__ d1Wih, const float* __restrict__ d1Whh,
    const float* __restrict__ d1bih, const float* __restrict__ d1bhh,
    const float* __restrict__ projb) {
    const size_t FULL = (size_t)N4 * Hd;
    long long idx = (long long)blockIdx.x * 256 + threadIdx.x;

    if (idx < (long long)(6 * FULL)) {
        int seg = (int)(idx / FULL);
        size_t i = (size_t)(idx % FULL);
        int r = (int)(i / Hd), k = (int)(i % Hd);
        size_t dst = (size_t)remap_row(r) * Hd + k;
        const float* src; bf16* dh; bf16* dl;
        switch (seg) {
            case 0: src = e0Whh; dh = gB_h0h;  dl = gB_h0l;  break;
            case 1: src = e1Wih; dh = gB_x1h;  dl = gB_x1l;  break;
            case 2: src = e1Whh; dh = gB_h1h;  dl = gB_h1l;  break;
            case 3: src = d0Whh; dh = gB_d0h;  dl = gB_d0l;  break;
            case 4: src = d1Wih; dh = gB_x1dh; dl = gB_x1dl; break;
            default: src = d1Whh; dh = gB_d1h; dl = gB_d1l;  break;
        }
        split_store(src[i], dh, dl, dst);
        return;
    }
    idx -= 6LL * FULL;

    if (idx < (long long)N4 * Fin) {   // Wx0
        size_t i = (size_t)idx;
        int r = (int)(i / Fin), k = (int)(i % Fin);
        split_store(e0Wih[i], gB_x0h, gB_x0l, (size_t)remap_row(r) * Fin + k);
        return;
    }
    idx -= (long long)N4 * Fin;

    if (idx < (long long)Bsz * T_IN * Fin) {   // x -> [t][b][f] hi/lo
        size_t i = (size_t)idx;
        int b = (int)(i / (T_IN * Fin));
        int t = (int)((i / Fin) % T_IN);
        int f = (int)(i % Fin);
        split_store(x[i], g_xch, g_xcl, (size_t)t * Bsz * Fin + b * Fin + f);
        return;
    }
    idx -= (long long)Bsz * T_IN * Fin;

    if (idx < N4) {                    // biases + Wv, remapped
        int r = (int)idx;
        int dst = remap_row(r);
        g_Wv[dst]  = d0Wih[r];
        g_b0[dst]  = e0bih[r] + e0bhh[r];
        g_b1[dst]  = e1bih[r] + e1bhh[r];
        g_bd0[dst] = d0bih[r] + d0bhh[r];
        g_bd1[dst] = d1bih[r] + d1bhh[r];
        return;
    }
    idx -= N4;

    if (idx < Bsz) {                   // prev slot0 = x[:, -1, -1]; slot1 = projb seed
        g_pacc[0][idx] = x[(size_t)(idx + 1) * T_IN * Fin - 1];
        g_pacc[1][idx] = projb[0];
        return;
    }
    idx -= Bsz;
    if (idx == 0) g_cnt = 0;
}

// ------------------------------ main kernel --------------------------------
__global__ void __launch_bounds__(THR, 1)
main_kernel(const float* __restrict__ projW,
            const float* __restrict__ projb,
            float* __restrict__ out) {
    extern __shared__ char dsm_raw[];
    const uint32_t raw32 = smem_u32(dsm_raw);
    const uint32_t dsm32 = (raw32 + 1023u) & ~1023u;

    const int tid  = threadIdx.x;
    const int lane = tid & 31;
    const int w    = tid >> 5;
    const int wm   = w & 3;
    const int wn   = w >> 2;
    const int bid  = blockIdx.x;
    const int mT   = bid >> 5;
    const int nT   = bid & 31;
    const int bm   = mT * 64;
    const int colb = nT * 64;
    const int G    = nT * 2 + wn;

    float accA[4][4], accB[4][4];
    float c0[4], c1[4];
#pragma unroll
    for (int d = 0; d < 4; ++d) { c0[d] = 0.0f; c1[d] = 0.0f; }

    Seg segs[4];

    // -------- fused encoder wavefront: superstep s = enc0(s) + enc1(s-1) ----
    for (int s = 0; s <= T_IN; ++s) {
        int ns = 0, split = 0;
        if (s < T_IN) {
            segs[ns++] = { g_xch + (size_t)s * Bsz * Fin,
                           g_xcl + (size_t)s * Bsz * Fin,
                           gB_x0h, gB_x0l, Fin };
            if (s) segs[ns++] = { g_hsh + (size_t)(s - 1) * BH,
                                  g_hsl + (size_t)(s - 1) * BH,
                                  gB_h0h, gB_h0l, Hd };
            split = s ? 9 : 1;
        }
        if (s >= 1) {
            segs[ns++] = { g_hsh + (size_t)(s - 1) * BH,
                           g_hsl + (size_t)(s - 1) * BH,
                           gB_x1h, gB_x1l, Hd };
            if (s >= 2) segs[ns++] = { &g_h1h[s & 1][0], &g_h1l[s & 1][0],
                                       gB_h1h, gB_h1l, Hd };
        }
        ZERO_ACC(accA); ZERO_ACC(accB);
        pipe_gemm(dsm32, segs, ns, split, accA, accB, bm, colb, tid, lane, wm, wn);
        if (s < T_IN)
            epilogue_lstm(accA, c0, g_b0, nullptr, nullptr,
                          g_hsh + (size_t)s * BH, g_hsl + (size_t)s * BH,
                          nullptr, nullptr, bm, G, wm, lane);
        if (s >= 1)
            epilogue_lstm(accB, c1, g_b1, nullptr, nullptr,
                          &g_h1h[(s - 1) & 1][0], &g_h1l[(s - 1) & 1][0],
                          nullptr, nullptr, bm, G, wm, lane);
        grid_sync();
    }

    // -------------------------------- decoder -------------------------------
    const bf16 *h0h = g_hsh + (size_t)(T_IN - 1) * BH;
    const bf16 *h0l = g_hsl + (size_t)(T_IN - 1) * BH;
    const bf16 *h1h = &g_h1h[(T_IN - 1) & 1][0];
    const bf16 *h1l = &g_h1l[(T_IN - 1) & 1][0];
    const float pjb = projb[0];

    for (int t = 0; t < T_OUT; ++t) {
        // phase A: dec0(t); side tasks: emit out[:,t-1], reseed next slot
        if (bid == 0 && tid < Bsz && t >= 1)
            out[(size_t)tid * T_OUT + (t - 1)] = g_pacc[t & 1][tid];
        if (bid == 1 && tid < Bsz)
            g_pacc[(t + 1) & 1][tid] = pjb;

        segs[0] = { h0h, h0l, gB_d0h, gB_d0l, Hd };
        ZERO_ACC(accA);
        pipe_gemm(dsm32, segs, 1, 8, accA, accA, bm, colb, tid, lane, wm, wn);
        epilogue_lstm(accA, c0, g_bd0, &g_pacc[t & 1][0], g_Wv,
                      &g_d0h[t & 1][0], &g_d0l[t & 1][0],
                      nullptr, nullptr, bm, G, wm, lane);
        grid_sync();

        // phase B: dec1(t) + fused projection into pacc[(t+1)&1]
        segs[0] = { &g_d0h[t & 1][0], &g_d0l[t & 1][0], gB_x1dh, gB_x1dl, Hd };
        segs[1] = { h1h, h1l, gB_d1h, gB_d1l, Hd };
        ZERO_ACC(accA);
        pipe_gemm(dsm32, segs, 2, 16, accA, accA, bm, colb, tid, lane, wm, wn);
        epilogue_lstm(accA, c1, g_bd1, nullptr, nullptr,
                      &g_d1h[t & 1][0], &g_d1l[t & 1][0],
                      projW, &g_pacc[(t + 1) & 1][0], bm, G, wm, lane);
        grid_sync();

        h0h = &g_d0h[t & 1][0]; h0l = &g_d0l[t & 1][0];
        h1h = &g_d1h[t & 1][0]; h1l = &g_d1l[t & 1][0];
    }

    // final output column (t = 63): slot (63+1)&1 = 0
    if (bid == 0 && tid < Bsz)
        out[(size_t)tid * T_OUT + (T_OUT - 1)] = g_pacc[0][tid];
}

// ------------------------------- host side ---------------------------------
extern "C" void kernel_launch(void* const* d_in, const int* in_sizes, int n_in,
                              void* d_out, int out_size) {
    const float* x      = (const float*)d_in[0];
    const float* e0Wih  = (const float*)d_in[2];
    const float* e0Whh  = (const float*)d_in[3];
    const float* e0bih  = (const float*)d_in[4];
    const float* e0bhh  = (const float*)d_in[5];
    const float* e1Wih  = (const float*)d_in[6];
    const float* e1Whh  = (const float*)d_in[7];
    const float* e1bih  = (const float*)d_in[8];
    const float* e1bhh  = (const float*)d_in[9];
    const float* d0Wih  = (const float*)d_in[10];
    const float* d0Whh  = (const float*)d_in[11];
    const float* d0bih  = (const float*)d_in[12];
    const float* d0bhh  = (const float*)d_in[13];
    const float* d1Wih  = (const float*)d_in[14];
    const float* d1Whh  = (const float*)d_in[15];
    const float* d1bih  = (const float*)d_in[16];
    const float* d1bhh  = (const float*)d_in[17];
    const float* projW  = (const float*)d_in[18];
    const float* projb  = (const float*)d_in[19];
    float* out = (float*)d_out;

    const long long total = 6LL * N4 * Hd + (long long)N4 * Fin
                          + (long long)Bsz * T_IN * Fin + N4 + Bsz + 1;
    const int nblk = (int)((total + 255) / 256);
    prep_kernel<<<nblk, 256>>>(x,
        e0Wih, e0Whh, e0bih, e0bhh,
        e1Wih, e1Whh, e1bih, e1bhh,
        d0Wih, d0Whh, d0bih, d0bhh,
        d1Wih, d1Whh, d1bih, d1bhh, projb);

    cudaFuncSetAttribute(main_kernel, cudaFuncAttributeMaxDynamicSharedMemorySize, DSMEM);
    main_kernel<<<NBLK, THR, DSMEM>>>(projW, projb, out);
}

// round 7
// speedup vs baseline: 2.7856x; 1.0186x over previous
#include <cuda_runtime.h>
#include <cuda_bf16.h>
#include <cstdint>
#include <math.h>

// ---------------------------------------------------------------------------
// Seq2Seq LSTM via mma.sync (HMMA bf16): B=256, T_in=512, F=64, H=512, T_out=64
// Round 7: split accumulators (hh vs cross terms) to break MMA dependency
// chains; 6-stage cp.async ring processing chunk PAIRS (one syncthreads per
// 2 chunks). Encoder wavefront fusion + fused projection retained.
// 128 persistent CTAs (4M x 32N tiles), 256 threads.
// ---------------------------------------------------------------------------

using bf16 = __nv_bfloat16;

#define Bsz   256
#define Hd    512
#define Fin   64
#define T_IN  512
#define T_OUT 64
#define N4    2048
#define BH    (Bsz*Hd)
#define NBLK  128
#define THR   256

// per-stage smem: A_hi 8K | A_lo 8K | B_hi 8K | B_lo 8K
#define OFF_AL 8192
#define OFF_BH 16384
#define OFF_BL 24576
#define BUFB   32768
#define NSTAGE 6
#define DSMEM  (NSTAGE*BUFB + 1024)

// ------------------------- device scratch (static) -------------------------
__device__ __align__(16) bf16 g_xch[(size_t)T_IN * Bsz * Fin];
__device__ __align__(16) bf16 g_xcl[(size_t)T_IN * Bsz * Fin];
__device__ __align__(16) bf16 g_hsh[(size_t)T_IN * BH];
__device__ __align__(16) bf16 g_hsl[(size_t)T_IN * BH];
__device__ __align__(16) bf16 g_h1h[2][BH], g_h1l[2][BH];
__device__ __align__(16) bf16 g_d0h[2][BH], g_d0l[2][BH];
__device__ __align__(16) bf16 g_d1h[2][BH], g_d1l[2][BH];
__device__ float g_pacc[2][Bsz];          // proj ping-pong accumulators

// weights, remapped rows: row' = (j>>3)*32 + g*8 + (j&7), layout [2048][K]
__device__ __align__(16) bf16 gB_x0h[N4 * Fin], gB_x0l[N4 * Fin];
__device__ __align__(16) bf16 gB_h0h[N4 * Hd],  gB_h0l[N4 * Hd];
__device__ __align__(16) bf16 gB_x1h[N4 * Hd],  gB_x1l[N4 * Hd];
__device__ __align__(16) bf16 gB_h1h[N4 * Hd],  gB_h1l[N4 * Hd];
__device__ __align__(16) bf16 gB_d0h[N4 * Hd],  gB_d0l[N4 * Hd];
__device__ __align__(16) bf16 gB_x1dh[N4 * Hd], gB_x1dl[N4 * Hd];
__device__ __align__(16) bf16 gB_d1h[N4 * Hd],  gB_d1l[N4 * Hd];

__device__ __align__(16) float g_b0[N4], g_b1[N4], g_bd0[N4], g_bd1[N4], g_Wv[N4];

__device__ unsigned g_cnt;
__device__ volatile unsigned g_gen;

// ------------------------------- asm helpers -------------------------------
#define LDSM4(R, A) \
    asm volatile("ldmatrix.sync.aligned.m8n8.x4.shared.b16 {%0,%1,%2,%3}, [%4];" \
        : "=r"((R)[0]), "=r"((R)[1]), "=r"((R)[2]), "=r"((R)[3]) : "r"(A))

#define MMA(D, A, B) \
    asm volatile("mma.sync.aligned.m16n8k16.row.col.f32.bf16.bf16.f32 " \
        "{%0,%1,%2,%3}, {%4,%5,%6,%7}, {%8,%9}, {%0,%1,%2,%3};" \
        : "+f"((D)[0]), "+f"((D)[1]), "+f"((D)[2]), "+f"((D)[3]) \
        : "r"((A)[0]), "r"((A)[1]), "r"((A)[2]), "r"((A)[3]), \
          "r"((B)[0]), "r"((B)[1]))

#define CP16(sa, ga) \
    asm volatile("cp.async.cg.shared.global [%0], [%1], 16;" :: "r"(sa), "l"(ga))
#define CP_COMMIT() asm volatile("cp.async.commit_group;")
#define CP_WAIT0()  asm volatile("cp.async.wait_group 0;" ::: "memory")
#define CP_WAIT1()  asm volatile("cp.async.wait_group 1;" ::: "memory")

__device__ __forceinline__ uint32_t smem_u32(const void* p) {
    uint32_t a;
    asm("{ .reg .u64 t; cvta.to.shared.u64 t, %1; cvt.u32.u64 %0, t; }"
        : "=r"(a) : "l"(p));
    return a;
}
__device__ __forceinline__ float sigf(float x) { return 1.0f / (1.0f + expf(-x)); }

__device__ __forceinline__ void grid_sync() {
    __syncthreads();
    if (threadIdx.x == 0) {
        __threadfence();
        unsigned g = g_gen;
        unsigned old = atomicAdd(&g_cnt, 1u);
        if (old == NBLK - 1) {
            g_cnt = 0;
            __threadfence();
            g_gen = g + 1;
        } else {
            while (g_gen == g) __nanosleep(64);
            __threadfence();
        }
    }
    __syncthreads();
}

// ----------------------------- GEMM machinery ------------------------------
struct Seg {
    const bf16 *Ah, *Al;   // A [row][K]
    const bf16 *Bh, *Bl;   // B' [2048][K]
    int K;                 // 64 or 512
};

// Issue one K=64 chunk into ring stage `st` via cp.async
__device__ __forceinline__ void issue_chunk(uint32_t dsm32, int st, const Seg* segs,
                                            int c, int bm, int colb, int tid) {
    int ck = c, si = 0;
    int n = segs[0].K >> 6;
    while (ck >= n) { ck -= n; ++si; n = segs[si].K >> 6; }
    const Seg sp = segs[si];
    const uint32_t base = dsm32 + st * BUFB;
    const int K = sp.K;
#pragma unroll
    for (int i = 0; i < 2; ++i) {
        const int uu = tid * 2 + i;
        const int row = uu >> 3, seg = uu & 7;
        const int off = uu * 16;
        const int sw = off ^ ((off >> 3) & 0x70);
        const bf16* gah = sp.Ah + (size_t)(bm + row) * K + ck * 64 + seg * 8;
        const bf16* gal = sp.Al + (size_t)(bm + row) * K + ck * 64 + seg * 8;
        CP16(base + sw, gah);
        CP16(base + OFF_AL + sw, gal);
        const bf16* gbh = sp.Bh + (size_t)(colb + row) * K + ck * 64 + seg * 8;
        const bf16* gbl = sp.Bl + (size_t)(colb + row) * K + ck * 64 + seg * 8;
        CP16(base + OFF_BH + sw, gbh);
        CP16(base + OFF_BL + sw, gbl);
    }
}

// Split accumulators: accP += Ah*Bh ; accC += Ah*Bl + Al*Bh
__device__ __forceinline__ void compute_chunk(uint32_t sbase,
                                              float accP[4][4], float accC[4][4],
                                              int lane, int wm, int wn) {
    const uint32_t sA  = sbase;
    const uint32_t sAl = sbase + OFF_AL;
    const uint32_t sB  = sbase + OFF_BH;
    const uint32_t sBl = sbase + OFF_BL;
    const int abase = (wm * 16 + (lane & 15)) * 128 + ((lane >> 4) << 4);
    const int bbase0 = (wn * 32 + (lane & 7) + ((lane >> 4) << 3)) * 128
                     + (((lane >> 3) & 1) << 4);
#pragma unroll
    for (int ka = 0; ka < 4; ++ka) {
        uint32_t ah[4], al[4], bh[8], bl[8];
        const int ao = abase + ka * 32;
        const int asw = ao ^ ((ao >> 3) & 0x70);
        LDSM4(ah, sA + asw);
        LDSM4(al, sAl + asw);
        const int bo0 = bbase0 + ka * 32;
        const int bo1 = bo0 + 16 * 128;
        const int bsw0 = bo0 ^ ((bo0 >> 3) & 0x70);
        const int bsw1 = bo1 ^ ((bo1 >> 3) & 0x70);
        LDSM4(bh, sB + bsw0);
        LDSM4(bh + 4, sB + bsw1);
        LDSM4(bl, sBl + bsw0);
        LDSM4(bl + 4, sBl + bsw1);
#pragma unroll
        for (int a = 0; a < 4; ++a) {
            MMA(accP[a], ah, bh + 2 * a);
            MMA(accC[a], ah, bl + 2 * a);
            MMA(accC[a], al, bh + 2 * a);
        }
    }
}

// 6-stage ring, processed in chunk PAIRS: one wait + one syncthreads per pair.
// chunks < split accumulate into (aP,aC); rest into (bP,bC).
__device__ __forceinline__ void pipe_gemm(uint32_t dsm32, const Seg* segs, int nseg,
                                          int split,
                                          float aP[4][4], float aC[4][4],
                                          float bP[4][4], float bC[4][4],
                                          int bm, int colb, int tid, int lane,
                                          int wm, int wn) {
    int tot = 0;
    for (int i = 0; i < nseg; ++i) tot += segs[i].K >> 6;
    const int npairs = (tot + 1) >> 1;

    // prefill pairs 0,1
    issue_chunk(dsm32, 0, segs, 0, bm, colb, tid);
    if (1 < tot) issue_chunk(dsm32, 1, segs, 1, bm, colb, tid);
    CP_COMMIT();
    if (npairs > 1) {
        issue_chunk(dsm32, 2, segs, 2, bm, colb, tid);
        if (3 < tot) issue_chunk(dsm32, 3, segs, 3, bm, colb, tid);
        CP_COMMIT();
    }

    for (int p = 0; p < npairs; ++p) {
        if (p + 1 < npairs) CP_WAIT1();
        else                CP_WAIT0();
        __syncthreads();
        if (p + 2 < npairs) {
            const int q = 2 * (p + 2);
            issue_chunk(dsm32, q % NSTAGE, segs, q, bm, colb, tid);
            if (q + 1 < tot)
                issue_chunk(dsm32, (q + 1) % NSTAGE, segs, q + 1, bm, colb, tid);
            CP_COMMIT();
        }
        const int c0i = 2 * p;
        {
            const uint32_t sb = dsm32 + (c0i % NSTAGE) * BUFB;
            if (c0i < split) compute_chunk(sb, aP, aC, lane, wm, wn);
            else             compute_chunk(sb, bP, bC, lane, wm, wn);
        }
        if (c0i + 1 < tot) {
            const uint32_t sb = dsm32 + ((c0i + 1) % NSTAGE) * BUFB;
            if (c0i + 1 < split) compute_chunk(sb, aP, aC, lane, wm, wn);
            else                 compute_chunk(sb, bP, bC, lane, wm, wn);
        }
    }
}

#define ZERO_ACC(A) \
    do { _Pragma("unroll") for (int _a = 0; _a < 4; ++_a) \
         _Pragma("unroll") for (int _d = 0; _d < 4; ++_d) (A)[_a][_d] = 0.0f; } while (0)

#define SUM_ACC(P, C) \
    do { _Pragma("unroll") for (int _a = 0; _a < 4; ++_a) \
         _Pragma("unroll") for (int _d = 0; _d < 4; ++_d) (P)[_a][_d] += (C)[_a][_d]; } while (0)

// LSTM pointwise epilogue: thread owns rows {m, m+8} x units {u0,u0+1} for all
// 4 gates. Optionally fuses the projection partial-dot (atomicAdd into pacc).
__device__ __forceinline__ void epilogue_lstm(float acc[4][4], float* c,
                                              const float* bias,
                                              const float* prevv, const float* Wv,
                                              bf16* Hh, bf16* Hl,
                                              const float* pjW, float* pacc,
                                              int bm, int G, int wm, int lane) {
    const int q = lane & 3, r = lane >> 2;
    const float2* b2 = (const float2*)bias;
    float2 bb[4];
#pragma unroll
    for (int g = 0; g < 4; ++g) bb[g] = b2[G * 16 + g * 4 + q];
    float2 wv[4];
    if (Wv) {
        const float2* w2 = (const float2*)Wv;
#pragma unroll
        for (int g = 0; g < 4; ++g) wv[g] = w2[G * 16 + g * 4 + q];
    }
    float rsum[2] = {0.0f, 0.0f};
#pragma unroll
    for (int rr = 0; rr < 2; ++rr) {
        const int m = bm + wm * 16 + r + rr * 8;
        float pv = 0.0f;
        if (prevv) pv = prevv[m];
        uint32_t ph, pl;
#pragma unroll
        for (int p = 0; p < 2; ++p) {
            const int d = rr * 2 + p;
            float gi = acc[0][d] + (p ? bb[0].y : bb[0].x);
            float gf = acc[1][d] + (p ? bb[1].y : bb[1].x);
            float gg = acc[2][d] + (p ? bb[2].y : bb[2].x);
            float go = acc[3][d] + (p ? bb[3].y : bb[3].x);
            if (Wv) {
                gi = fmaf(pv, p ? wv[0].y : wv[0].x, gi);
                gf = fmaf(pv, p ? wv[1].y : wv[1].x, gf);
                gg = fmaf(pv, p ? wv[2].y : wv[2].x, gg);
                go = fmaf(pv, p ? wv[3].y : wv[3].x, go);
            }
            float cn = sigf(gf) * c[d] + sigf(gi) * tanhf(gg);
            float hn = sigf(go) * tanhf(cn);
            c[d] = cn;
            if (pjW) rsum[rr] = fmaf(hn, pjW[G * 8 + 2 * q + p], rsum[rr]);
            bf16 hh = __float2bfloat16(hn);
            bf16 hl = __float2bfloat16(hn - __bfloat162float(hh));
            uint32_t uh = (uint32_t)__bfloat16_as_ushort(hh) << (p * 16);
            uint32_t ul = (uint32_t)__bfloat16_as_ushort(hl) << (p * 16);
            if (p == 0) { ph = uh; pl = ul; }
            else        { ph |= uh; pl |= ul; }
        }
        const size_t hb = (size_t)m * Hd + G * 8 + 2 * q;
        *(uint32_t*)(Hh + hb) = ph;
        *(uint32_t*)(Hl + hb) = pl;
    }
    if (pjW) {
#pragma unroll
        for (int rr = 0; rr < 2; ++rr) {
            rsum[rr] += __shfl_xor_sync(0xffffffffu, rsum[rr], 1);
            rsum[rr] += __shfl_xor_sync(0xffffffffu, rsum[rr], 2);
        }
        if (q == 0) {
            atomicAdd(&pacc[bm + wm * 16 + r], rsum[0]);
            atomicAdd(&pacc[bm + wm * 16 + r + 8], rsum[1]);
        }
    }
}

// ------------------------------- prep kernel -------------------------------
__device__ __forceinline__ void split_store(float v, bf16* h, bf16* l, size_t i) {
    bf16 hi = __float2bfloat16(v);
    h[i] = hi;
    l[i] = __float2bfloat16(v - __bfloat162float(hi));
}
__device__ __forceinline__ int remap_row(int r) {
    const int g = r >> 9, j = r & 511;
    return ((j >> 3) << 5) + (g << 3) + (j & 7);
}

__global__ void prep_kernel(
    const float* __restrict__ x,
    const float* __restrict__ e0Wih, const float* __restrict__ e0Whh,
    const float* __restrict__ e0bih, const float* __restrict__ e0bhh,
    const float* __restrict__ e1Wih, const float* __restrict__ e1Whh,
    const float* __restrict__ e1bih, const float* __restrict__ e1bhh,
    const float* __restrict__ d0Wih, const float* __restrict__ d0Whh,
    const float* __restrict__ d0bih, const float* __restrict__ d0bhh,
    const float* __restrict__ d1Wih, const float* __restrict__ d1Whh,
    const float* __restrict__ d1bih, const float* __restrict__ d1bhh,
    const float* __restrict__ projb) {
    const size_t FULL = (size_t)N4 * Hd;
    long long idx = (long long)blockIdx.x * 256 + threadIdx.x;

    if (idx < (long long)(6 * FULL)) {
        int seg = (int)(idx / FULL);
        size_t i = (size_t)(idx % FULL);
        int r = (int)(i / Hd), k = (int)(i % Hd);
        size_t dst = (size_t)remap_row(r) * Hd + k;
        const float* src; bf16* dh; bf16* dl;
        switch (seg) {
            case 0: src = e0Whh; dh = gB_h0h;  dl = gB_h0l;  break;
            case 1: src = e1Wih; dh = gB_x1h;  dl = gB_x1l;  break;
            case 2: src = e1Whh; dh = gB_h1h;  dl = gB_h1l;  break;
            case 3: src = d0Whh; dh = gB_d0h;  dl = gB_d0l;  break;
            case 4: src = d1Wih; dh = gB_x1dh; dl = gB_x1dl; break;
            default: src = d1Whh; dh = gB_d1h; dl = gB_d1l;  break;
        }
        split_store(src[i], dh, dl, dst);
        return;
    }
    idx -= 6LL * FULL;

    if (idx < (long long)N4 * Fin) {   // Wx0
        size_t i = (size_t)idx;
        int r = (int)(i / Fin), k = (int)(i % Fin);
        split_store(e0Wih[i], gB_x0h, gB_x0l, (size_t)remap_row(r) * Fin + k);
        return;
    }
    idx -= (long long)N4 * Fin;

    if (idx < (long long)Bsz * T_IN * Fin) {   // x -> [t][b][f] hi/lo
        size_t i = (size_t)idx;
        int b = (int)(i / (T_IN * Fin));
        int t = (int)((i / Fin) % T_IN);
        int f = (int)(i % Fin);
        split_store(x[i], g_xch, g_xcl, (size_t)t * Bsz * Fin + b * Fin + f);
        return;
    }
    idx -= (long long)Bsz * T_IN * Fin;

    if (idx < N4) {                    // biases + Wv, remapped
        int r = (int)idx;
        int dst = remap_row(r);
        g_Wv[dst]  = d0Wih[r];
        g_b0[dst]  = e0bih[r] + e0bhh[r];
        g_b1[dst]  = e1bih[r] + e1bhh[r];
        g_bd0[dst] = d0bih[r] + d0bhh[r];
        g_bd1[dst] = d1bih[r] + d1bhh[r];
        return;
    }
    idx -= N4;

    if (idx < Bsz) {                   // prev slot0 = x[:, -1, -1]; slot1 = projb seed
        g_pacc[0][idx] = x[(size_t)(idx + 1) * T_IN * Fin - 1];
        g_pacc[1][idx] = projb[0];
        return;
    }
    idx -= Bsz;
    if (idx == 0) g_cnt = 0;
}

// ------------------------------ main kernel --------------------------------
__global__ void __launch_bounds__(THR, 1)
main_kernel(const float* __restrict__ projW,
            const float* __restrict__ projb,
            float* __restrict__ out) {
    extern __shared__ char dsm_raw[];
    const uint32_t raw32 = smem_u32(dsm_raw);
    const uint32_t dsm32 = (raw32 + 1023u) & ~1023u;

    const int tid  = threadIdx.x;
    const int lane = tid & 31;
    const int w    = tid >> 5;
    const int wm   = w & 3;
    const int wn   = w >> 2;
    const int bid  = blockIdx.x;
    const int mT   = bid >> 5;
    const int nT   = bid & 31;
    const int bm   = mT * 64;
    const int colb = nT * 64;
    const int G    = nT * 2 + wn;

    float accAP[4][4], accAC[4][4], accBP[4][4], accBC[4][4];
    float c0[4], c1[4];
#pragma unroll
    for (int d = 0; d < 4; ++d) { c0[d] = 0.0f; c1[d] = 0.0f; }

    Seg segs[4];

    // -------- fused encoder wavefront: superstep s = enc0(s) + enc1(s-1) ----
    for (int s = 0; s <= T_IN; ++s) {
        int ns = 0, split = 0;
        if (s < T_IN) {
            segs[ns++] = { g_xch + (size_t)s * Bsz * Fin,
                           g_xcl + (size_t)s * Bsz * Fin,
                           gB_x0h, gB_x0l, Fin };
            if (s) segs[ns++] = { g_hsh + (size_t)(s - 1) * BH,
                                  g_hsl + (size_t)(s - 1) * BH,
                                  gB_h0h, gB_h0l, Hd };
            split = s ? 9 : 1;
        }
        if (s >= 1) {
            segs[ns++] = { g_hsh + (size_t)(s - 1) * BH,
                           g_hsl + (size_t)(s - 1) * BH,
                           gB_x1h, gB_x1l, Hd };
            if (s >= 2) segs[ns++] = { &g_h1h[s & 1][0], &g_h1l[s & 1][0],
                                       gB_h1h, gB_h1l, Hd };
        }
        ZERO_ACC(accAP); ZERO_ACC(accAC); ZERO_ACC(accBP); ZERO_ACC(accBC);
        pipe_gemm(dsm32, segs, ns, split, accAP, accAC, accBP, accBC,
                  bm, colb, tid, lane, wm, wn);
        if (s < T_IN) {
            SUM_ACC(accAP, accAC);
            epilogue_lstm(accAP, c0, g_b0, nullptr, nullptr,
                          g_hsh + (size_t)s * BH, g_hsl + (size_t)s * BH,
                          nullptr, nullptr, bm, G, wm, lane);
        }
        if (s >= 1) {
            SUM_ACC(accBP, accBC);
            epilogue_lstm(accBP, c1, g_b1, nullptr, nullptr,
                          &g_h1h[(s - 1) & 1][0], &g_h1l[(s - 1) & 1][0],
                          nullptr, nullptr, bm, G, wm, lane);
        }
        grid_sync();
    }

    // -------------------------------- decoder -------------------------------
    const bf16 *h0h = g_hsh + (size_t)(T_IN - 1) * BH;
    const bf16 *h0l = g_hsl + (size_t)(T_IN - 1) * BH;
    const bf16 *h1h = &g_h1h[(T_IN - 1) & 1][0];
    const bf16 *h1l = &g_h1l[(T_IN - 1) & 1][0];
    const float pjb = projb[0];

    for (int t = 0; t < T_OUT; ++t) {
        // phase A: dec0(t); side tasks: emit out[:,t-1], reseed next slot
        if (bid == 0 && tid < Bsz && t >= 1)
            out[(size_t)tid * T_OUT + (t - 1)] = g_pacc[t & 1][tid];
        if (bid == 1 && tid < Bsz)
            g_pacc[(t + 1) & 1][tid] = pjb;

        segs[0] = { h0h, h0l, gB_d0h, gB_d0l, Hd };
        ZERO_ACC(accAP); ZERO_ACC(accAC);
        pipe_gemm(dsm32, segs, 1, 8, accAP, accAC, accAP, accAC,
                  bm, colb, tid, lane, wm, wn);
        SUM_ACC(accAP, accAC);
        epilogue_lstm(accAP, c0, g_bd0, &g_pacc[t & 1][0], g_Wv,
                      &g_d0h[t & 1][0], &g_d0l[t & 1][0],
                      nullptr, nullptr, bm, G, wm, lane);
        grid_sync();

        // phase B: dec1(t) + fused projection into pacc[(t+1)&1]
        segs[0] = { &g_d0h[t & 1][0], &g_d0l[t & 1][0], gB_x1dh, gB_x1dl, Hd };
        segs[1] = { h1h, h1l, gB_d1h, gB_d1l, Hd };
        ZERO_ACC(accAP); ZERO_ACC(accAC);
        pipe_gemm(dsm32, segs, 2, 16, accAP, accAC, accAP, accAC,
                  bm, colb, tid, lane, wm, wn);
        SUM_ACC(accAP, accAC);
        epilogue_lstm(accAP, c1, g_bd1, nullptr, nullptr,
                      &g_d1h[t & 1][0], &g_d1l[t & 1][0],
                      projW, &g_pacc[(t + 1) & 1][0], bm, G, wm, lane);
        grid_sync();

        h0h = &g_d0h[t & 1][0]; h0l = &g_d0l[t & 1][0];
        h1h = &g_d1h[t & 1][0]; h1l = &g_d1l[t & 1][0];
    }

    // final output column (t = 63): slot (63+1)&1 = 0
    if (bid == 0 && tid < Bsz)
        out[(size_t)tid * T_OUT + (T_OUT - 1)] = g_pacc[0][tid];
}

// ------------------------------- host side ---------------------------------
extern "C" void kernel_launch(void* const* d_in, const int* in_sizes, int n_in,
                              void* d_out, int out_size) {
    const float* x      = (const float*)d_in[0];
    const float* e0Wih  = (const float*)d_in[2];
    const float* e0Whh  = (const float*)d_in[3];
    const float* e0bih  = (const float*)d_in[4];
    const float* e0bhh  = (const float*)d_in[5];
    const float* e1Wih  = (const float*)d_in[6];
    const float* e1Whh  = (const float*)d_in[7];
    const float* e1bih  = (const float*)d_in[8];
    const float* e1bhh  = (const float*)d_in[9];
    const float* d0Wih  = (const float*)d_in[10];
    const float* d0Whh  = (const float*)d_in[11];
    const float* d0bih  = (const float*)d_in[12];
    const float* d0bhh  = (const float*)d_in[13];
    const float* d1Wih  = (const float*)d_in[14];
    const float* d1Whh  = (const float*)d_in[15];
    const float* d1bih  = (const float*)d_in[16];
    const float* d1bhh  = (const float*)d_in[17];
    const float* projW  = (const float*)d_in[18];
    const float* projb  = (const float*)d_in[19];
    float* out = (float*)d_out;

    const long long total = 6LL * N4 * Hd + (long long)N4 * Fin
                          + (long long)Bsz * T_IN * Fin + N4 + Bsz + 1;
    const int nblk = (int)((total + 255) / 256);
    prep_kernel<<<nblk, 256>>>(x,
        e0Wih, e0Whh, e0bih, e0bhh,
        e1Wih, e1Whh, e1bih, e1bhh,
        d0Wih, d0Whh, d0bih, d0bhh,
        d1Wih, d1Whh, d1bih, d1bhh, projb);

    cudaFuncSetAttribute(main_kernel, cudaFuncAttributeMaxDynamicSharedMemorySize, DSMEM);
    main_kernel<<<NBLK, THR, DSMEM>>>(projW, projb, out);
}

// round 8
// speedup vs baseline: 2.8073x; 1.0078x over previous
#include <cuda_runtime.h>
#include <cuda_bf16.h>
#include <cstdint>
#include <math.h>

// ---------------------------------------------------------------------------
// Seq2Seq LSTM via mma.sync (HMMA bf16): B=256, T_in=512, F=64, H=512, T_out=64
// Round 8: 512 threads/CTA (16 warps, 4/SMSP) with 16x16 warp tiles to double
// latency hiding. Gate remap col = 16*(j>>2) + 2*(j&3) + (g&1) + 8*(g>>1):
// each thread's D-fragment holds all 4 gates of one unit. Split accumulators,
// 6-stage cp.async ring (pairs), encoder wavefront fusion, fused projection.
// ---------------------------------------------------------------------------

using bf16 = __nv_bfloat16;

#define Bsz   256
#define Hd    512
#define Fin   64
#define T_IN  512
#define T_OUT 64
#define N4    2048
#define BH    (Bsz*Hd)
#define NBLK  128
#define THR   512

// per-stage smem: A_hi 8K | A_lo 8K | B_hi 8K | B_lo 8K
#define OFF_AL 8192
#define OFF_BH 16384
#define OFF_BL 24576
#define BUFB   32768
#define NSTAGE 6
#define DSMEM  (NSTAGE*BUFB + 1024)

// ------------------------- device scratch (static) -------------------------
__device__ __align__(16) bf16 g_xch[(size_t)T_IN * Bsz * Fin];
__device__ __align__(16) bf16 g_xcl[(size_t)T_IN * Bsz * Fin];
__device__ __align__(16) bf16 g_hsh[(size_t)T_IN * BH];
__device__ __align__(16) bf16 g_hsl[(size_t)T_IN * BH];
__device__ __align__(16) bf16 g_h1h[2][BH], g_h1l[2][BH];
__device__ __align__(16) bf16 g_d0h[2][BH], g_d0l[2][BH];
__device__ __align__(16) bf16 g_d1h[2][BH], g_d1l[2][BH];
__device__ float g_pacc[2][Bsz];          // proj ping-pong accumulators

// weights, remapped rows (see remap_row), layout [2048][K] bf16 hi/lo
__device__ __align__(16) bf16 gB_x0h[N4 * Fin], gB_x0l[N4 * Fin];
__device__ __align__(16) bf16 gB_h0h[N4 * Hd],  gB_h0l[N4 * Hd];
__device__ __align__(16) bf16 gB_x1h[N4 * Hd],  gB_x1l[N4 * Hd];
__device__ __align__(16) bf16 gB_h1h[N4 * Hd],  gB_h1l[N4 * Hd];
__device__ __align__(16) bf16 gB_d0h[N4 * Hd],  gB_d0l[N4 * Hd];
__device__ __align__(16) bf16 gB_x1dh[N4 * Hd], gB_x1dl[N4 * Hd];
__device__ __align__(16) bf16 gB_d1h[N4 * Hd],  gB_d1l[N4 * Hd];

__device__ __align__(16) float g_b0[N4], g_b1[N4], g_bd0[N4], g_bd1[N4], g_Wv[N4];

__device__ unsigned g_cnt;
__device__ volatile unsigned g_gen;

// ------------------------------- asm helpers -------------------------------
#define LDSM4(R, A) \
    asm volatile("ldmatrix.sync.aligned.m8n8.x4.shared.b16 {%0,%1,%2,%3}, [%4];" \
        : "=r"((R)[0]), "=r"((R)[1]), "=r"((R)[2]), "=r"((R)[3]) : "r"(A))

#define MMA(D, A, B) \
    asm volatile("mma.sync.aligned.m16n8k16.row.col.f32.bf16.bf16.f32 " \
        "{%0,%1,%2,%3}, {%4,%5,%6,%7}, {%8,%9}, {%0,%1,%2,%3};" \
        : "+f"((D)[0]), "+f"((D)[1]), "+f"((D)[2]), "+f"((D)[3]) \
        : "r"((A)[0]), "r"((A)[1]), "r"((A)[2]), "r"((A)[3]), \
          "r"((B)[0]), "r"((B)[1]))

#define CP16(sa, ga) \
    asm volatile("cp.async.cg.shared.global [%0], [%1], 16;" :: "r"(sa), "l"(ga))
#define CP_COMMIT() asm volatile("cp.async.commit_group;")
#define CP_WAIT0()  asm volatile("cp.async.wait_group 0;" ::: "memory")
#define CP_WAIT1()  asm volatile("cp.async.wait_group 1;" ::: "memory")

__device__ __forceinline__ uint32_t smem_u32(const void* p) {
    uint32_t a;
    asm("{ .reg .u64 t; cvta.to.shared.u64 t, %1; cvt.u32.u64 %0, t; }"
        : "=r"(a) : "l"(p));
    return a;
}
__device__ __forceinline__ float sigf(float x) { return 1.0f / (1.0f + expf(-x)); }

__device__ __forceinline__ void grid_sync() {
    __syncthreads();
    if (threadIdx.x == 0) {
        __threadfence();
        unsigned g = g_gen;
        unsigned old = atomicAdd(&g_cnt, 1u);
        if (old == NBLK - 1) {
            g_cnt = 0;
            __threadfence();
            g_gen = g + 1;
        } else {
            while (g_gen == g) __nanosleep(64);
            __threadfence();
        }
    }
    __syncthreads();
}

// ----------------------------- GEMM machinery ------------------------------
struct Seg {
    const bf16 *Ah, *Al;   // A [row][K]
    const bf16 *Bh, *Bl;   // B' [2048][K]
    int K;                 // 64 or 512
};

// Issue one K=64 chunk into ring stage `st`: 512 threads, 1x16B per region each
__device__ __forceinline__ void issue_chunk(uint32_t dsm32, int st, const Seg* segs,
                                            int c, int bm, int colb, int tid) {
    int ck = c, si = 0;
    int n = segs[0].K >> 6;
    while (ck >= n) { ck -= n; ++si; n = segs[si].K >> 6; }
    const Seg sp = segs[si];
    const uint32_t base = dsm32 + st * BUFB;
    const int K = sp.K;
    const int row = tid >> 3, seg = tid & 7;
    const int off = tid * 16;
    const int sw = off ^ ((off >> 3) & 0x70);
    const bf16* gah = sp.Ah + (size_t)(bm + row) * K + ck * 64 + seg * 8;
    const bf16* gal = sp.Al + (size_t)(bm + row) * K + ck * 64 + seg * 8;
    CP16(base + sw, gah);
    CP16(base + OFF_AL + sw, gal);
    const bf16* gbh = sp.Bh + (size_t)(colb + row) * K + ck * 64 + seg * 8;
    const bf16* gbl = sp.Bl + (size_t)(colb + row) * K + ck * 64 + seg * 8;
    CP16(base + OFF_BH + sw, gbh);
    CP16(base + OFF_BL + sw, gbl);
}

// Warp tile 16x16: accP += Ah*Bh ; accC += Ah*Bl + Al*Bh
__device__ __forceinline__ void compute_chunk(uint32_t sbase,
                                              float accP[2][4], float accC[2][4],
                                              int lane, int wm, int wn) {
    const uint32_t sA  = sbase;
    const uint32_t sAl = sbase + OFF_AL;
    const uint32_t sB  = sbase + OFF_BH;
    const uint32_t sBl = sbase + OFF_BL;
    const int abase = (wm * 16 + (lane & 15)) * 128 + ((lane >> 4) << 4);
    const int bbase = (wn * 16 + (lane & 7) + ((lane >> 4) << 3)) * 128
                    + (((lane >> 3) & 1) << 4);
#pragma unroll
    for (int ka = 0; ka < 4; ++ka) {
        uint32_t ah[4], al[4], bh[4], bl[4];
        const int ao = abase + ka * 32;
        const int asw = ao ^ ((ao >> 3) & 0x70);
        LDSM4(ah, sA + asw);
        LDSM4(al, sAl + asw);
        const int bo = bbase + ka * 32;
        const int bsw = bo ^ ((bo >> 3) & 0x70);
        LDSM4(bh, sB + bsw);
        LDSM4(bl, sBl + bsw);
#pragma unroll
        for (int a = 0; a < 2; ++a) {
            MMA(accP[a], ah, bh + 2 * a);
            MMA(accC[a], ah, bl + 2 * a);
            MMA(accC[a], al, bh + 2 * a);
        }
    }
}

// 6-stage ring, chunk PAIRS: one wait + one syncthreads per 2 chunks.
__device__ __forceinline__ void pipe_gemm(uint32_t dsm32, const Seg* segs, int nseg,
                                          int split,
                                          float aP[2][4], float aC[2][4],
                                          float bP[2][4], float bC[2][4],
                                          int bm, int colb, int tid, int lane,
                                          int wm, int wn) {
    int tot = 0;
    for (int i = 0; i < nseg; ++i) tot += segs[i].K >> 6;
    const int npairs = (tot + 1) >> 1;

    issue_chunk(dsm32, 0, segs, 0, bm, colb, tid);
    if (1 < tot) issue_chunk(dsm32, 1, segs, 1, bm, colb, tid);
    CP_COMMIT();
    if (npairs > 1) {
        issue_chunk(dsm32, 2, segs, 2, bm, colb, tid);
        if (3 < tot) issue_chunk(dsm32, 3, segs, 3, bm, colb, tid);
        CP_COMMIT();
    }

    for (int p = 0; p < npairs; ++p) {
        if (p + 1 < npairs) CP_WAIT1();
        else                CP_WAIT0();
        __syncthreads();
        if (p + 2 < npairs) {
            const int q = 2 * (p + 2);
            issue_chunk(dsm32, q % NSTAGE, segs, q, bm, colb, tid);
            if (q + 1 < tot)
                issue_chunk(dsm32, (q + 1) % NSTAGE, segs, q + 1, bm, colb, tid);
            CP_COMMIT();
        }
        const int c0i = 2 * p;
        {
            const uint32_t sb = dsm32 + (c0i % NSTAGE) * BUFB;
            if (c0i < split) compute_chunk(sb, aP, aC, lane, wm, wn);
            else             compute_chunk(sb, bP, bC, lane, wm, wn);
        }
        if (c0i + 1 < tot) {
            const uint32_t sb = dsm32 + ((c0i + 1) % NSTAGE) * BUFB;
            if (c0i + 1 < split) compute_chunk(sb, aP, aC, lane, wm, wn);
            else                 compute_chunk(sb, bP, bC, lane, wm, wn);
        }
    }
}

#define ZERO_ACC(A) \
    do { _Pragma("unroll") for (int _a = 0; _a < 2; ++_a) \
         _Pragma("unroll") for (int _d = 0; _d < 4; ++_d) (A)[_a][_d] = 0.0f; } while (0)

#define SUM_ACC(P, C) \
    do { _Pragma("unroll") for (int _a = 0; _a < 2; ++_a) \
         _Pragma("unroll") for (int _d = 0; _d < 4; ++_d) (P)[_a][_d] += (C)[_a][_d]; } while (0)

// Epilogue: thread owns rows {m, m+8} x ONE unit (all 4 gates).
// acc[0][rr*2+p]: p=0 -> gate i, p=1 -> gate f; acc[1][..]: p=0 -> g, p=1 -> o.
__device__ __forceinline__ void epilogue_lstm(float acc[2][4], float* c,
                                              const float* bias,
                                              const float* prevv, const float* Wv,
                                              bf16* Hh, bf16* Hl,
                                              const float* pjW, float* pacc,
                                              int bm, int G16, int wm, int lane) {
    const int q = lane & 3, r = lane >> 2;
    const float2* b2 = (const float2*)bias;
    const float2 bIF = b2[G16 * 8 + q];
    const float2 bGO = b2[G16 * 8 + 4 + q];
    float2 wIF = make_float2(0.f, 0.f), wGO = make_float2(0.f, 0.f);
    if (Wv) {
        const float2* w2 = (const float2*)Wv;
        wIF = w2[G16 * 8 + q];
        wGO = w2[G16 * 8 + 4 + q];
    }
    const int u = G16 * 4 + q;      // original hidden-unit index
    float pw = 0.0f;
    if (pjW) pw = pjW[u];
    float rsum[2] = {0.0f, 0.0f};
#pragma unroll
    for (int rr = 0; rr < 2; ++rr) {
        const int m = bm + wm * 16 + r + rr * 8;
        float gi = acc[0][rr * 2 + 0] + bIF.x;
        float gf = acc[0][rr * 2 + 1] + bIF.y;
        float gg = acc[1][rr * 2 + 0] + bGO.x;
        float go = acc[1][rr * 2 + 1] + bGO.y;
        if (prevv) {
            const float pv = prevv[m];
            gi = fmaf(pv, wIF.x, gi); gf = fmaf(pv, wIF.y, gf);
            gg = fmaf(pv, wGO.x, gg); go = fmaf(pv, wGO.y, go);
        }
        float cn = sigf(gf) * c[rr] + sigf(gi) * tanhf(gg);
        float hn = sigf(go) * tanhf(cn);
        c[rr] = cn;
        if (pjW) rsum[rr] = hn * pw;
        bf16 hh = __float2bfloat16(hn);
        bf16 hl = __float2bfloat16(hn - __bfloat162float(hh));
        const size_t hb = (size_t)m * Hd + u;
        Hh[hb] = hh;
        Hl[hb] = hl;
    }
    if (pjW) {
#pragma unroll
        for (int rr = 0; rr < 2; ++rr) {
            rsum[rr] += __shfl_xor_sync(0xffffffffu, rsum[rr], 1);
            rsum[rr] += __shfl_xor_sync(0xffffffffu, rsum[rr], 2);
        }
        if (q == 0) {
            atomicAdd(&pacc[bm + wm * 16 + r], rsum[0]);
            atomicAdd(&pacc[bm + wm * 16 + r + 8], rsum[1]);
        }
    }
}

// ------------------------------- prep kernel -------------------------------
__device__ __forceinline__ void split_store(float v, bf16* h, bf16* l, size_t i) {
    bf16 hi = __float2bfloat16(v);
    h[i] = hi;
    l[i] = __float2bfloat16(v - __bfloat162float(hi));
}
// gate g (0..3), unit j (0..511) -> col = 16*(j>>2) + 2*(j&3) + (g&1) + 8*(g>>1)
__device__ __forceinline__ int remap_row(int r) {
    const int g = r >> 9, j = r & 511;
    return ((j >> 2) << 4) + ((j & 3) << 1) + (g & 1) + ((g >> 1) << 3);
}

__global__ void prep_kernel(
    const float* __restrict__ x,
    const float* __restrict__ e0Wih, const float* __restrict__ e0Whh,
    const float* __restrict__ e0bih, const float* __restrict__ e0bhh,
    const float* __restrict__ e1Wih, const float* __restrict__ e1Whh,
    const float* __restrict__ e1bih, const float* __restrict__ e1bhh,
    const float* __restrict__ d0Wih, const float* __restrict__ d0Whh,
    const float* __restrict__ d0bih, const float* __restrict__ d0bhh,
    const float* __restrict__ d1Wih, const float* __restrict__ d1Whh,
    const float* __restrict__ d1bih, const float* __restrict__ d1bhh,
    const float* __restrict__ projb) {
    const size_t FULL = (size_t)N4 * Hd;
    long long idx = (long long)blockIdx.x * 256 + threadIdx.x;

    if (idx < (long long)(6 * FULL)) {
        int seg = (int)(idx / FULL);
        size_t i = (size_t)(idx % FULL);
        int r = (int)(i / Hd), k = (int)(i % Hd);
        size_t dst = (size_t)remap_row(r) * Hd + k;
        const float* src; bf16* dh; bf16* dl;
        switch (seg) {
            case 0: src = e0Whh; dh = gB_h0h;  dl = gB_h0l;  break;
            case 1: src = e1Wih; dh = gB_x1h;  dl = gB_x1l;  break;
            case 2: src = e1Whh; dh = gB_h1h;  dl = gB_h1l;  break;
            case 3: src = d0Whh; dh = gB_d0h;  dl = gB_d0l;  break;
            case 4: src = d1Wih; dh = gB_x1dh; dl = gB_x1dl; break;
            default: src = d1Whh; dh = gB_d1h; dl = gB_d1l;  break;
        }
        split_store(src[i], dh, dl, dst);
        return;
    }
    idx -= 6LL * FULL;

    if (idx < (long long)N4 * Fin) {   // Wx0
        size_t i = (size_t)idx;
        int r = (int)(i / Fin), k = (int)(i % Fin);
        split_store(e0Wih[i], gB_x0h, gB_x0l, (size_t)remap_row(r) * Fin + k);
        return;
    }
    idx -= (long long)N4 * Fin;

    if (idx < (long long)Bsz * T_IN * Fin) {   // x -> [t][b][f] hi/lo
        size_t i = (size_t)idx;
        int b = (int)(i / (T_IN * Fin));
        int t = (int)((i / Fin) % T_IN);
        int f = (int)(i % Fin);
        split_store(x[i], g_xch, g_xcl, (size_t)t * Bsz * Fin + b * Fin + f);
        return;
    }
    idx -= (long long)Bsz * T_IN * Fin;

    if (idx < N4) {                    // biases + Wv, remapped
        int r = (int)idx;
        int dst = remap_row(r);
        g_Wv[dst]  = d0Wih[r];
        g_b0[dst]  = e0bih[r] + e0bhh[r];
        g_b1[dst]  = e1bih[r] + e1bhh[r];
        g_bd0[dst] = d0bih[r] + d0bhh[r];
        g_bd1[dst] = d1bih[r] + d1bhh[r];
        return;
    }
    idx -= N4;

    if (idx < Bsz) {                   // prev slot0 = x[:, -1, -1]; slot1 = projb seed
        g_pacc[0][idx] = x[(size_t)(idx + 1) * T_IN * Fin - 1];
        g_pacc[1][idx] = projb[0];
        return;
    }
    idx -= Bsz;
    if (idx == 0) g_cnt = 0;
}

// ------------------------------ main kernel --------------------------------
__global__ void __launch_bounds__(THR, 1)
main_kernel(const float* __restrict__ projW,
            const float* __restrict__ projb,
            float* __restrict__ out) {
    extern __shared__ char dsm_raw[];
    const uint32_t raw32 = smem_u32(dsm_raw);
    const uint32_t dsm32 = (raw32 + 1023u) & ~1023u;

    const int tid  = threadIdx.x;
    const int lane = tid & 31;
    const int w    = tid >> 5;         // 0..15
    const int wm   = w & 3;            // M slice (16 rows)
    const int wn   = w >> 2;           // N slice (16 cols)
    const int bid  = blockIdx.x;       // 128 CTAs: 4M x 32N
    const int mT   = bid >> 5;
    const int nT   = bid & 31;
    const int bm   = mT * 64;
    const int colb = nT * 64;
    const int G16  = nT * 4 + wn;      // 16-col block = 4 units x 4 gates

    float accAP[2][4], accAC[2][4], accBP[2][4], accBC[2][4];
    float c0[2], c1[2];
    c0[0] = c0[1] = c1[0] = c1[1] = 0.0f;

    Seg segs[4];

    // -------- fused encoder wavefront: superstep s = enc0(s) + enc1(s-1) ----
    for (int s = 0; s <= T_IN; ++s) {
        int ns = 0, split = 0;
        if (s < T_IN) {
            segs[ns++] = { g_xch + (size_t)s * Bsz * Fin,
                           g_xcl + (size_t)s * Bsz * Fin,
                           gB_x0h, gB_x0l, Fin };
            if (s) segs[ns++] = { g_hsh + (size_t)(s - 1) * BH,
                                  g_hsl + (size_t)(s - 1) * BH,
                                  gB_h0h, gB_h0l, Hd };
            split = s ? 9 : 1;
        }
        if (s >= 1) {
            segs[ns++] = { g_hsh + (size_t)(s - 1) * BH,
                           g_hsl + (size_t)(s - 1) * BH,
                           gB_x1h, gB_x1l, Hd };
            if (s >= 2) segs[ns++] = { &g_h1h[s & 1][0], &g_h1l[s & 1][0],
                                       gB_h1h, gB_h1l, Hd };
        }
        ZERO_ACC(accAP); ZERO_ACC(accAC); ZERO_ACC(accBP); ZERO_ACC(accBC);
        pipe_gemm(dsm32, segs, ns, split, accAP, accAC, accBP, accBC,
                  bm, colb, tid, lane, wm, wn);
        if (s < T_IN) {
            SUM_ACC(accAP, accAC);
            epilogue_lstm(accAP, c0, g_b0, nullptr, nullptr,
                          g_hsh + (size_t)s * BH, g_hsl + (size_t)s * BH,
                          nullptr, nullptr, bm, G16, wm, lane);
        }
        if (s >= 1) {
            SUM_ACC(accBP, accBC);
            epilogue_lstm(accBP, c1, g_b1, nullptr, nullptr,
                          &g_h1h[(s - 1) & 1][0], &g_h1l[(s - 1) & 1][0],
                          nullptr, nullptr, bm, G16, wm, lane);
        }
        grid_sync();
    }

    // -------------------------------- decoder -------------------------------
    const bf16 *h0h = g_hsh + (size_t)(T_IN - 1) * BH;
    const bf16 *h0l = g_hsl + (size_t)(T_IN - 1) * BH;
    const bf16 *h1h = &g_h1h[(T_IN - 1) & 1][0];
    const bf16 *h1l = &g_h1l[(T_IN - 1) & 1][0];
    const float pjb = projb[0];

    for (int t = 0; t < T_OUT; ++t) {
        // phase A: dec0(t); side tasks: emit out[:,t-1], reseed next slot
        if (bid == 0 && tid < Bsz && t >= 1)
            out[(size_t)tid * T_OUT + (t - 1)] = g_pacc[t & 1][tid];
        if (bid == 1 && tid < Bsz)
            g_pacc[(t + 1) & 1][tid] = pjb;

        segs[0] = { h0h, h0l, gB_d0h, gB_d0l, Hd };
        ZERO_ACC(accAP); ZERO_ACC(accAC);
        pipe_gemm(dsm32, segs, 1, 8, accAP, accAC, accAP, accAC,
                  bm, colb, tid, lane, wm, wn);
        SUM_ACC(accAP, accAC);
        epilogue_lstm(accAP, c0, g_bd0, &g_pacc[t & 1][0], g_Wv,
                      &g_d0h[t & 1][0], &g_d0l[t & 1][0],
                      nullptr, nullptr, bm, G16, wm, lane);
        grid_sync();

        // phase B: dec1(t) + fused projection into pacc[(t+1)&1]
        segs[0] = { &g_d0h[t & 1][0], &g_d0l[t & 1][0], gB_x1dh, gB_x1dl, Hd };
        segs[1] = { h1h, h1l, gB_d1h, gB_d1l, Hd };
        ZERO_ACC(accAP); ZERO_ACC(accAC);
        pipe_gemm(dsm32, segs, 2, 16, accAP, accAC, accAP, accAC,
                  bm, colb, tid, lane, wm, wn);
        SUM_ACC(accAP, accAC);
        epilogue_lstm(accAP, c1, g_bd1, nullptr, nullptr,
                      &g_d1h[t & 1][0], &g_d1l[t & 1][0],
                      projW, &g_pacc[(t + 1) & 1][0], bm, G16, wm, lane);
        grid_sync();

        h0h = &g_d0h[t & 1][0]; h0l = &g_d0l[t & 1][0];
        h1h = &g_d1h[t & 1][0]; h1l = &g_d1l[t & 1][0];
    }

    // final output column (t = 63): slot (63+1)&1 = 0
    if (bid == 0 && tid < Bsz)
        out[(size_t)tid * T_OUT + (T_OUT - 1)] = g_pacc[0][tid];
}

// ------------------------------- host side ---------------------------------
extern "C" void kernel_launch(void* const* d_in, const int* in_sizes, int n_in,
                              void* d_out, int out_size) {
    const float* x      = (const float*)d_in[0];
    const float* e0Wih  = (const float*)d_in[2];
    const float* e0Whh  = (const float*)d_in[3];
    const float* e0bih  = (const float*)d_in[4];
    const float* e0bhh  = (const float*)d_in[5];
    const float* e1Wih  = (const float*)d_in[6];
    const float* e1Whh  = (const float*)d_in[7];
    const float* e1bih  = (const float*)d_in[8];
    const float* e1bhh  = (const float*)d_in[9];
    const float* d0Wih  = (const float*)d_in[10];
    const float* d0Whh  = (const float*)d_in[11];
    const float* d0bih  = (const float*)d_in[12];
    const float* d0bhh  = (const float*)d_in[13];
    const float* d1Wih  = (const float*)d_in[14];
    const float* d1Whh  = (const float*)d_in[15];
    const float* d1bih  = (const float*)d_in[16];
    const float* d1bhh  = (const float*)d_in[17];
    const float* projW  = (const float*)d_in[18];
    const float* projb  = (const float*)d_in[19];
    float* out = (float*)d_out;

    const long long total = 6LL * N4 * Hd + (long long)N4 * Fin
                          + (long long)Bsz * T_IN * Fin + N4 + Bsz + 1;
    const int nblk = (int)((total + 255) / 256);
    prep_kernel<<<nblk, 256>>>(x,
        e0Wih, e0Whh, e0bih, e0bhh,
        e1Wih, e1Whh, e1bih, e1bhh,
        d0Wih, d0Whh, d0bih, d0bhh,
        d1Wih, d1Whh, d1bih, d1bhh, projb);

    cudaFuncSetAttribute(main_kernel, cudaFuncAttributeMaxDynamicSharedMemorySize, DSMEM);
    main_kernel<<<NBLK, THR, DSMEM>>>(projW, projb, out);
}

// round 9
// speedup vs baseline: 3.7987x; 1.3532x over previous
#include <cuda_runtime.h>
#include <cuda_fp16.h>
#include <cstdint>
#include <math.h>

// ---------------------------------------------------------------------------
// Seq2Seq LSTM via mma.sync (HMMA fp16): B=256, T_in=512, F=64, H=512, T_out=64
// Round 9: SINGLE-PASS fp16 (no hi/lo split). Error budget: 3-pass bf16 gave
// 7e-6; fp16 single-pass scales to ~4.5e-4 < 1e-3. Per-chunk work drops ~3x.
// 128 persistent CTAs (4M x 32N), 512 threads (16 warps, 16x16 tiles),
// 8-stage cp.async ring in pairs (lookahead 3), encoder wavefront fusion,
// fused projection. Gate remap col = 16*(j>>2)+2*(j&3)+(g&1)+8*(g>>1).
// ---------------------------------------------------------------------------

using f16 = __half;

#define Bsz   256
#define Hd    512
#define Fin   64
#define T_IN  512
#define T_OUT 64
#define N4    2048
#define BH    (Bsz*Hd)
#define NBLK  128
#define THR   512

// per-stage smem: A 8K | B 8K
#define OFF_B  8192
#define BUFB   16384
#define NSTAGE 8
#define DSMEM  (NSTAGE*BUFB + 1024)

// ------------------------- device scratch (static) -------------------------
__device__ __align__(16) f16 g_xc[(size_t)T_IN * Bsz * Fin];
__device__ __align__(16) f16 g_hs[(size_t)T_IN * BH];
__device__ __align__(16) f16 g_h1[2][BH];
__device__ __align__(16) f16 g_d0[2][BH];
__device__ __align__(16) f16 g_d1[2][BH];
__device__ float g_pacc[2][Bsz];          // proj ping-pong accumulators

// weights, remapped rows (see remap_row), layout [2048][K] fp16
__device__ __align__(16) f16 gB_x0[N4 * Fin];
__device__ __align__(16) f16 gB_h0[N4 * Hd];
__device__ __align__(16) f16 gB_x1[N4 * Hd];
__device__ __align__(16) f16 gB_h1[N4 * Hd];
__device__ __align__(16) f16 gB_d0[N4 * Hd];
__device__ __align__(16) f16 gB_x1d[N4 * Hd];
__device__ __align__(16) f16 gB_d1[N4 * Hd];

__device__ __align__(16) float g_b0[N4], g_b1[N4], g_bd0[N4], g_bd1[N4], g_Wv[N4];

__device__ unsigned g_cnt;
__device__ volatile unsigned g_gen;

// ------------------------------- asm helpers -------------------------------
#define LDSM4(R, A) \
    asm volatile("ldmatrix.sync.aligned.m8n8.x4.shared.b16 {%0,%1,%2,%3}, [%4];" \
        : "=r"((R)[0]), "=r"((R)[1]), "=r"((R)[2]), "=r"((R)[3]) : "r"(A))

#define MMA(D, A, B) \
    asm volatile("mma.sync.aligned.m16n8k16.row.col.f32.f16.f16.f32 " \
        "{%0,%1,%2,%3}, {%4,%5,%6,%7}, {%8,%9}, {%0,%1,%2,%3};" \
        : "+f"((D)[0]), "+f"((D)[1]), "+f"((D)[2]), "+f"((D)[3]) \
        : "r"((A)[0]), "r"((A)[1]), "r"((A)[2]), "r"((A)[3]), \
          "r"((B)[0]), "r"((B)[1]))

#define CP16(sa, ga) \
    asm volatile("cp.async.cg.shared.global [%0], [%1], 16;" :: "r"(sa), "l"(ga))
#define CP_COMMIT() asm volatile("cp.async.commit_group;")
#define CP_WAIT0()  asm volatile("cp.async.wait_group 0;" ::: "memory")
#define CP_WAIT1()  asm volatile("cp.async.wait_group 1;" ::: "memory")
#define CP_WAIT2()  asm volatile("cp.async.wait_group 2;" ::: "memory")

__device__ __forceinline__ uint32_t smem_u32(const void* p) {
    uint32_t a;
    asm("{ .reg .u64 t; cvta.to.shared.u64 t, %1; cvt.u32.u64 %0, t; }"
        : "=r"(a) : "l"(p));
    return a;
}
__device__ __forceinline__ float sigf(float x) { return 1.0f / (1.0f + expf(-x)); }

__device__ __forceinline__ void grid_sync() {
    __syncthreads();
    if (threadIdx.x == 0) {
        __threadfence();
        unsigned g = g_gen;
        unsigned old = atomicAdd(&g_cnt, 1u);
        if (old == NBLK - 1) {
            g_cnt = 0;
            __threadfence();
            g_gen = g + 1;
        } else {
            while (g_gen == g) __nanosleep(64);
            __threadfence();
        }
    }
    __syncthreads();
}

// ----------------------------- GEMM machinery ------------------------------
struct Seg {
    const f16 *A;   // A [row][K]
    const f16 *B;   // B' [2048][K]
    int K;          // 64 or 512
};

// Issue one K=64 chunk (A 64x64 + B 64x64 fp16 = 16KB) into ring stage `st`.
// 512 threads: each does one 16B A piece and one 16B B piece.
__device__ __forceinline__ void issue_chunk(uint32_t dsm32, int st, const Seg* segs,
                                            int c, int bm, int colb, int tid) {
    int ck = c, si = 0;
    int n = segs[0].K >> 6;
    while (ck >= n) { ck -= n; ++si; n = segs[si].K >> 6; }
    const Seg sp = segs[si];
    const uint32_t base = dsm32 + st * BUFB;
    const int K = sp.K;
    const int row = tid >> 3, seg = tid & 7;
    const int off = tid * 16;
    const int sw = off ^ ((off >> 3) & 0x70);
    CP16(base + sw, sp.A + (size_t)(bm + row) * K + ck * 64 + seg * 8);
    CP16(base + OFF_B + sw, sp.B + (size_t)(colb + row) * K + ck * 64 + seg * 8);
}

// Warp tile 16x16, single pass fp16
__device__ __forceinline__ void compute_chunk(uint32_t sbase, float acc[2][4],
                                              int lane, int wm, int wn) {
    const uint32_t sA = sbase;
    const uint32_t sB = sbase + OFF_B;
    const int abase = (wm * 16 + (lane & 15)) * 128 + ((lane >> 4) << 4);
    const int bbase = (wn * 16 + (lane & 7) + ((lane >> 4) << 3)) * 128
                    + (((lane >> 3) & 1) << 4);
#pragma unroll
    for (int ka = 0; ka < 4; ++ka) {
        uint32_t a[4], b[4];
        const int ao = abase + ka * 32;
        const int asw = ao ^ ((ao >> 3) & 0x70);
        LDSM4(a, sA + asw);
        const int bo = bbase + ka * 32;
        const int bsw = bo ^ ((bo >> 3) & 0x70);
        LDSM4(b, sB + bsw);
        MMA(acc[0], a, b);
        MMA(acc[1], a, b + 2);
    }
}

// 8-stage ring, chunk PAIRS, lookahead 3 pairs (wait_group 2).
__device__ __forceinline__ void pipe_gemm(uint32_t dsm32, const Seg* segs, int nseg,
                                          int split, float aA[2][4], float aB[2][4],
                                          int bm, int colb, int tid, int lane,
                                          int wm, int wn) {
    int tot = 0;
    for (int i = 0; i < nseg; ++i) tot += segs[i].K >> 6;
    const int npairs = (tot + 1) >> 1;
    const int prefill = npairs < 3 ? npairs : 3;
    for (int pp = 0; pp < prefill; ++pp) {
        issue_chunk(dsm32, (2 * pp) % NSTAGE, segs, 2 * pp, bm, colb, tid);
        if (2 * pp + 1 < tot)
            issue_chunk(dsm32, (2 * pp + 1) % NSTAGE, segs, 2 * pp + 1, bm, colb, tid);
        CP_COMMIT();
    }
    for (int p = 0; p < npairs; ++p) {
        const int ahead = npairs - 1 - p;
        if (ahead >= 2)      CP_WAIT2();
        else if (ahead == 1) CP_WAIT1();
        else                 CP_WAIT0();
        __syncthreads();
        if (p + 3 < npairs) {
            const int q = 2 * (p + 3);
            issue_chunk(dsm32, q % NSTAGE, segs, q, bm, colb, tid);
            if (q + 1 < tot)
                issue_chunk(dsm32, (q + 1) % NSTAGE, segs, q + 1, bm, colb, tid);
            CP_COMMIT();
        }
        const int c0i = 2 * p;
        {
            const uint32_t sb = dsm32 + (c0i % NSTAGE) * BUFB;
            compute_chunk(sb, c0i < split ? aA : aB, lane, wm, wn);
        }
        if (c0i + 1 < tot) {
            const uint32_t sb = dsm32 + ((c0i + 1) % NSTAGE) * BUFB;
            compute_chunk(sb, c0i + 1 < split ? aA : aB, lane, wm, wn);
        }
    }
}

#define ZERO_ACC(A) \
    do { _Pragma("unroll") for (int _a = 0; _a < 2; ++_a) \
         _Pragma("unroll") for (int _d = 0; _d < 4; ++_d) (A)[_a][_d] = 0.0f; } while (0)

// Epilogue: thread owns rows {m, m+8} x ONE unit (all 4 gates).
// acc[0][rr*2+p]: p=0 -> i, p=1 -> f; acc[1][..]: p=0 -> g, p=1 -> o.
__device__ __forceinline__ void epilogue_lstm(float acc[2][4], float* c,
                                              const float* bias,
                                              const float* prevv, const float* Wv,
                                              f16* H,
                                              const float* pjW, float* pacc,
                                              int bm, int G16, int wm, int lane) {
    const int q = lane & 3, r = lane >> 2;
    const float2* b2 = (const float2*)bias;
    const float2 bIF = b2[G16 * 8 + q];
    const float2 bGO = b2[G16 * 8 + 4 + q];
    float2 wIF = make_float2(0.f, 0.f), wGO = make_float2(0.f, 0.f);
    if (Wv) {
        const float2* w2 = (const float2*)Wv;
        wIF = w2[G16 * 8 + q];
        wGO = w2[G16 * 8 + 4 + q];
    }
    const int u = G16 * 4 + q;      // original hidden-unit index
    float pw = 0.0f;
    if (pjW) pw = pjW[u];
    float rsum[2] = {0.0f, 0.0f};
#pragma unroll
    for (int rr = 0; rr < 2; ++rr) {
        const int m = bm + wm * 16 + r + rr * 8;
        float gi = acc[0][rr * 2 + 0] + bIF.x;
        float gf = acc[0][rr * 2 + 1] + bIF.y;
        float gg = acc[1][rr * 2 + 0] + bGO.x;
        float go = acc[1][rr * 2 + 1] + bGO.y;
        if (prevv) {
            const float pv = prevv[m];
            gi = fmaf(pv, wIF.x, gi); gf = fmaf(pv, wIF.y, gf);
            gg = fmaf(pv, wGO.x, gg); go = fmaf(pv, wGO.y, go);
        }
        float cn = sigf(gf) * c[rr] + sigf(gi) * tanhf(gg);
        float hn = sigf(go) * tanhf(cn);
        c[rr] = cn;
        if (pjW) rsum[rr] = hn * pw;
        H[(size_t)m * Hd + u] = __float2half(hn);
    }
    if (pjW) {
#pragma unroll
        for (int rr = 0; rr < 2; ++rr) {
            rsum[rr] += __shfl_xor_sync(0xffffffffu, rsum[rr], 1);
            rsum[rr] += __shfl_xor_sync(0xffffffffu, rsum[rr], 2);
        }
        if (q == 0) {
            atomicAdd(&pacc[bm + wm * 16 + r], rsum[0]);
            atomicAdd(&pacc[bm + wm * 16 + r + 8], rsum[1]);
        }
    }
}

// ------------------------------- prep kernel -------------------------------
// gate g (0..3), unit j (0..511) -> col = 16*(j>>2) + 2*(j&3) + (g&1) + 8*(g>>1)
__device__ __forceinline__ int remap_row(int r) {
    const int g = r >> 9, j = r & 511;
    return ((j >> 2) << 4) + ((j & 3) << 1) + (g & 1) + ((g >> 1) << 3);
}

__global__ void prep_kernel(
    const float* __restrict__ x,
    const float* __restrict__ e0Wih, const float* __restrict__ e0Whh,
    const float* __restrict__ e0bih, const float* __restrict__ e0bhh,
    const float* __restrict__ e1Wih, const float* __restrict__ e1Whh,
    const float* __restrict__ e1bih, const float* __restrict__ e1bhh,
    const float* __restrict__ d0Wih, const float* __restrict__ d0Whh,
    const float* __restrict__ d0bih, const float* __restrict__ d0bhh,
    const float* __restrict__ d1Wih, const float* __restrict__ d1Whh,
    const float* __restrict__ d1bih, const float* __restrict__ d1bhh,
    const float* __restrict__ projb) {
    const size_t FULL = (size_t)N4 * Hd;
    long long idx = (long long)blockIdx.x * 256 + threadIdx.x;

    if (idx < (long long)(6 * FULL)) {
        int seg = (int)(idx / FULL);
        size_t i = (size_t)(idx % FULL);
        int r = (int)(i / Hd), k = (int)(i % Hd);
        size_t dst = (size_t)remap_row(r) * Hd + k;
        const float* src; f16* d;
        switch (seg) {
            case 0: src = e0Whh; d = gB_h0;  break;
            case 1: src = e1Wih; d = gB_x1;  break;
            case 2: src = e1Whh; d = gB_h1;  break;
            case 3: src = d0Whh; d = gB_d0;  break;
            case 4: src = d1Wih; d = gB_x1d; break;
            default: src = d1Whh; d = gB_d1; break;
        }
        d[dst] = __float2half(src[i]);
        return;
    }
    idx -= 6LL * FULL;

    if (idx < (long long)N4 * Fin) {   // Wx0
        size_t i = (size_t)idx;
        int r = (int)(i / Fin), k = (int)(i % Fin);
        gB_x0[(size_t)remap_row(r) * Fin + k] = __float2half(e0Wih[i]);
        return;
    }
    idx -= (long long)N4 * Fin;

    if (idx < (long long)Bsz * T_IN * Fin) {   // x -> [t][b][f]
        size_t i = (size_t)idx;
        int b = (int)(i / (T_IN * Fin));
        int t = (int)((i / Fin) % T_IN);
        int f = (int)(i % Fin);
        g_xc[(size_t)t * Bsz * Fin + b * Fin + f] = __float2half(x[i]);
        return;
    }
    idx -= (long long)Bsz * T_IN * Fin;

    if (idx < N4) {                    // biases + Wv, remapped (fp32)
        int r = (int)idx;
        int dst = remap_row(r);
        g_Wv[dst]  = d0Wih[r];
        g_b0[dst]  = e0bih[r] + e0bhh[r];
        g_b1[dst]  = e1bih[r] + e1bhh[r];
        g_bd0[dst] = d0bih[r] + d0bhh[r];
        g_bd1[dst] = d1bih[r] + d1bhh[r];
        return;
    }
    idx -= N4;

    if (idx < Bsz) {                   // prev slot0 = x[:, -1, -1]; slot1 = projb
        g_pacc[0][idx] = x[(size_t)(idx + 1) * T_IN * Fin - 1];
        g_pacc[1][idx] = projb[0];
        return;
    }
    idx -= Bsz;
    if (idx == 0) g_cnt = 0;
}

// ------------------------------ main kernel --------------------------------
__global__ void __launch_bounds__(THR, 1)
main_kernel(const float* __restrict__ projW,
            const float* __restrict__ projb,
            float* __restrict__ out) {
    extern __shared__ char dsm_raw[];
    const uint32_t raw32 = smem_u32(dsm_raw);
    const uint32_t dsm32 = (raw32 + 1023u) & ~1023u;

    const int tid  = threadIdx.x;
    const int lane = tid & 31;
    const int w    = tid >> 5;         // 0..15
    const int wm   = w & 3;            // M slice (16 rows)
    const int wn   = w >> 2;           // N slice (16 cols)
    const int bid  = blockIdx.x;       // 128 CTAs: 4M x 32N
    const int mT   = bid >> 5;
    const int nT   = bid & 31;
    const int bm   = mT * 64;
    const int colb = nT * 64;
    const int G16  = nT * 4 + wn;      // 16-col block = 4 units x 4 gates

    float accA[2][4], accB[2][4];
    float c0[2], c1[2];
    c0[0] = c0[1] = c1[0] = c1[1] = 0.0f;

    Seg segs[4];

    // -------- fused encoder wavefront: superstep s = enc0(s) + enc1(s-1) ----
    for (int s = 0; s <= T_IN; ++s) {
        int ns = 0, split = 0;
        if (s < T_IN) {
            segs[ns++] = { g_xc + (size_t)s * Bsz * Fin, gB_x0, Fin };
            if (s) segs[ns++] = { g_hs + (size_t)(s - 1) * BH, gB_h0, Hd };
            split = s ? 9 : 1;
        }
        if (s >= 1) {
            segs[ns++] = { g_hs + (size_t)(s - 1) * BH, gB_x1, Hd };
            if (s >= 2) segs[ns++] = { &g_h1[s & 1][0], gB_h1, Hd };
        }
        ZERO_ACC(accA); ZERO_ACC(accB);
        pipe_gemm(dsm32, segs, ns, split, accA, accB, bm, colb, tid, lane, wm, wn);
        if (s < T_IN)
            epilogue_lstm(accA, c0, g_b0, nullptr, nullptr,
                          g_hs + (size_t)s * BH, nullptr, nullptr, bm, G16, wm, lane);
        if (s >= 1)
            epilogue_lstm(accB, c1, g_b1, nullptr, nullptr,
                          &g_h1[(s - 1) & 1][0], nullptr, nullptr, bm, G16, wm, lane);
        grid_sync();
    }

    // -------------------------------- decoder -------------------------------
    const f16 *h0p = g_hs + (size_t)(T_IN - 1) * BH;
    const f16 *h1p = &g_h1[(T_IN - 1) & 1][0];
    const float pjb = projb[0];

    for (int t = 0; t < T_OUT; ++t) {
        // phase A: dec0(t); side tasks: emit out[:,t-1], reseed next slot
        if (bid == 0 && tid < Bsz && t >= 1)
            out[(size_t)tid * T_OUT + (t - 1)] = g_pacc[t & 1][tid];
        if (bid == 1 && tid < Bsz)
            g_pacc[(t + 1) & 1][tid] = pjb;

        segs[0] = { h0p, gB_d0, Hd };
        ZERO_ACC(accA);
        pipe_gemm(dsm32, segs, 1, 8, accA, accA, bm, colb, tid, lane, wm, wn);
        epilogue_lstm(accA, c0, g_bd0, &g_pacc[t & 1][0], g_Wv,
                      &g_d0[t & 1][0], nullptr, nullptr, bm, G16, wm, lane);
        grid_sync();

        // phase B: dec1(t) + fused projection into pacc[(t+1)&1]
        segs[0] = { &g_d0[t & 1][0], gB_x1d, Hd };
        segs[1] = { h1p, gB_d1, Hd };
        ZERO_ACC(accA);
        pipe_gemm(dsm32, segs, 2, 16, accA, accA, bm, colb, tid, lane, wm, wn);
        epilogue_lstm(accA, c1, g_bd1, nullptr, nullptr,
                      &g_d1[t & 1][0], projW, &g_pacc[(t + 1) & 1][0],
                      bm, G16, wm, lane);
        grid_sync();

        h0p = &g_d0[t & 1][0];
        h1p = &g_d1[t & 1][0];
    }

    // final output column (t = 63): slot (63+1)&1 = 0
    if (bid == 0 && tid < Bsz)
        out[(size_t)tid * T_OUT + (T_OUT - 1)] = g_pacc[0][tid];
}

// ------------------------------- host side ---------------------------------
extern "C" void kernel_launch(void* const* d_in, const int* in_sizes, int n_in,
                              void* d_out, int out_size) {
    const float* x      = (const float*)d_in[0];
    const float* e0Wih  = (const float*)d_in[2];
    const float* e0Whh  = (const float*)d_in[3];
    const float* e0bih  = (const float*)d_in[4];
    const float* e0bhh  = (const float*)d_in[5];
    const float* e1Wih  = (const float*)d_in[6];
    const float* e1Whh  = (const float*)d_in[7];
    const float* e1bih  = (const float*)d_in[8];
    const float* e1bhh  = (const float*)d_in[9];
    const float* d0Wih  = (const float*)d_in[10];
    const float* d0Whh  = (const float*)d_in[11];
    const float* d0bih  = (const float*)d_in[12];
    const float* d0bhh  = (const float*)d_in[13];
    const float* d1Wih  = (const float*)d_in[14];
    const float* d1Whh  = (const float*)d_in[15];
    const float* d1bih  = (const float*)d_in[16];
    const float* d1bhh  = (const float*)d_in[17];
    const float* projW  = (const float*)d_in[18];
    const float* projb  = (const float*)d_in[19];
    float* out = (float*)d_out;

    const long long total = 6LL * N4 * Hd + (long long)N4 * Fin
                          + (long long)Bsz * T_IN * Fin + N4 + Bsz + 1;
    const int nblk = (int)((total + 255) / 256);
    prep_kernel<<<nblk, 256>>>(x,
        e0Wih, e0Whh, e0bih, e0bhh,
        e1Wih, e1Whh, e1bih, e1bhh,
        d0Wih, d0Whh, d0bih, d0bhh,
        d1Wih, d1Whh, d1bih, d1bhh, projb);

    cudaFuncSetAttribute(main_kernel, cudaFuncAttributeMaxDynamicSharedMemorySize, DSMEM);
    main_kernel<<<NBLK, THR, DSMEM>>>(projW, projb, out);
}

// round 10
// speedup vs baseline: 4.2971x; 1.1312x over previous
#include <cuda_runtime.h>
#include <cuda_fp16.h>
#include <cstdint>
#include <math.h>

// ---------------------------------------------------------------------------
// Seq2Seq LSTM via mma.sync (HMMA fp16): B=256, T_in=512, F=64, H=512, T_out=64
// Round 10: hoist ALL address arithmetic out of the hot loops. Precomputed
// swizzled LDSM offsets, sequential issue cursor (no per-chunk segment search),
// precomputed cp.async row offsets. Otherwise identical to round 9:
// single-pass fp16, 128 CTAs (4M x 32N), 512 thr (16 warps, 16x16 tiles),
// 8-stage cp.async ring in pairs, encoder wavefront fusion, fused projection.
// ---------------------------------------------------------------------------

using f16 = __half;

#define Bsz   256
#define Hd    512
#define Fin   64
#define T_IN  512
#define T_OUT 64
#define N4    2048
#define BH    (Bsz*Hd)
#define NBLK  128
#define THR   512

// per-stage smem: A 8K | B 8K
#define OFF_B  8192
#define BUFB   16384
#define NSTAGE 8
#define DSMEM  (NSTAGE*BUFB + 1024)

// ------------------------- device scratch (static) -------------------------
__device__ __align__(16) f16 g_xc[(size_t)T_IN * Bsz * Fin];
__device__ __align__(16) f16 g_hs[(size_t)T_IN * BH];
__device__ __align__(16) f16 g_h1[2][BH];
__device__ __align__(16) f16 g_d0[2][BH];
__device__ __align__(16) f16 g_d1[2][BH];
__device__ float g_pacc[2][Bsz];          // proj ping-pong accumulators

// weights, remapped rows (see remap_row), layout [2048][K] fp16
__device__ __align__(16) f16 gB_x0[N4 * Fin];
__device__ __align__(16) f16 gB_h0[N4 * Hd];
__device__ __align__(16) f16 gB_x1[N4 * Hd];
__device__ __align__(16) f16 gB_h1[N4 * Hd];
__device__ __align__(16) f16 gB_d0[N4 * Hd];
__device__ __align__(16) f16 gB_x1d[N4 * Hd];
__device__ __align__(16) f16 gB_d1[N4 * Hd];

__device__ __align__(16) float g_b0[N4], g_b1[N4], g_bd0[N4], g_bd1[N4], g_Wv[N4];

__device__ unsigned g_cnt;
__device__ volatile unsigned g_gen;

// ------------------------------- asm helpers -------------------------------
#define LDSM4(R, A) \
    asm volatile("ldmatrix.sync.aligned.m8n8.x4.shared.b16 {%0,%1,%2,%3}, [%4];" \
        : "=r"((R)[0]), "=r"((R)[1]), "=r"((R)[2]), "=r"((R)[3]) : "r"(A))

#define MMA(D, A, B) \
    asm volatile("mma.sync.aligned.m16n8k16.row.col.f32.f16.f16.f32 " \
        "{%0,%1,%2,%3}, {%4,%5,%6,%7}, {%8,%9}, {%0,%1,%2,%3};" \
        : "+f"((D)[0]), "+f"((D)[1]), "+f"((D)[2]), "+f"((D)[3]) \
        : "r"((A)[0]), "r"((A)[1]), "r"((A)[2]), "r"((A)[3]), \
          "r"((B)[0]), "r"((B)[1]))

#define CP16(sa, ga) \
    asm volatile("cp.async.cg.shared.global [%0], [%1], 16;" :: "r"(sa), "l"(ga))
#define CP_COMMIT() asm volatile("cp.async.commit_group;")
#define CP_WAIT0()  asm volatile("cp.async.wait_group 0;" ::: "memory")
#define CP_WAIT1()  asm volatile("cp.async.wait_group 1;" ::: "memory")
#define CP_WAIT2()  asm volatile("cp.async.wait_group 2;" ::: "memory")

__device__ __forceinline__ uint32_t smem_u32(const void* p) {
    uint32_t a;
    asm("{ .reg .u64 t; cvta.to.shared.u64 t, %1; cvt.u32.u64 %0, t; }"
        : "=r"(a) : "l"(p));
    return a;
}
__device__ __forceinline__ float sigf(float x) { return 1.0f / (1.0f + expf(-x)); }

__device__ __forceinline__ void grid_sync() {
    __syncthreads();
    if (threadIdx.x == 0) {
        __threadfence();
        unsigned g = g_gen;
        unsigned old = atomicAdd(&g_cnt, 1u);
        if (old == NBLK - 1) {
            g_cnt = 0;
            __threadfence();
            g_gen = g + 1;
        } else {
            while (g_gen == g) __nanosleep(64);
            __threadfence();
        }
    }
    __syncthreads();
}

// ----------------------------- GEMM machinery ------------------------------
struct Seg {
    const f16 *A;   // A [row][K]
    const f16 *B;   // B' [2048][K]
    int K;          // 64 or 512
};

// Sequential issue cursor: chunks are always issued in order, so segment
// lookup is a cursor advance, and row offsets are precomputed per-thread.
struct Issue {
    const Seg* segs;
    int si, ck, c;            // segment idx, chunk within segment, global chunk
    uint32_t swA, swB;        // store offsets within a stage (swizzled, fixed)
    int ra64, ra512;          // A row offsets for K=64 / K=512
    int rb64, rb512;          // B row offsets
};

__device__ __forceinline__ Issue make_issue(const Seg* segs, int bm, int colb, int tid) {
    Issue st;
    st.segs = segs; st.si = 0; st.ck = 0; st.c = 0;
    const int row = tid >> 3, seg = tid & 7;
    const int off = tid * 16;
    const uint32_t sw = off ^ ((off >> 3) & 0x70);
    st.swA = sw;
    st.swB = OFF_B + sw;
    st.ra64  = (bm + row) * 64  + seg * 8;
    st.ra512 = (bm + row) * 512 + seg * 8;
    st.rb64  = (colb + row) * 64  + seg * 8;
    st.rb512 = (colb + row) * 512 + seg * 8;
    return st;
}

__device__ __forceinline__ void issue_next(Issue& st, uint32_t dsm32) {
    const Seg s = st.segs[st.si];
    const uint32_t base = dsm32 + (st.c & (NSTAGE - 1)) * BUFB;
    const int ko = st.ck * 64;
    const f16* ga = s.A + (s.K == 64 ? st.ra64 : st.ra512) + ko;
    const f16* gb = s.B + (s.K == 64 ? st.rb64 : st.rb512) + ko;
    CP16(base + st.swA, ga);
    CP16(base + st.swB, gb);
    ++st.c;
    if (++st.ck == (s.K >> 6)) { st.ck = 0; ++st.si; }
}

// Warp tile 16x16, single pass fp16; all LDSM offsets precomputed.
__device__ __forceinline__ void compute_chunk(uint32_t sbase, float acc[2][4],
                                              const uint32_t* asw,
                                              const uint32_t* bsw) {
#pragma unroll
    for (int ka = 0; ka < 4; ++ka) {
        uint32_t a[4], b[4];
        LDSM4(a, sbase + asw[ka]);
        LDSM4(b, sbase + bsw[ka]);
        MMA(acc[0], a, b);
        MMA(acc[1], a, b + 2);
    }
}

// 8-stage ring, chunk PAIRS, lookahead 3 pairs (wait_group 2).
__device__ __forceinline__ void pipe_gemm(uint32_t dsm32, const Seg* segs, int nseg,
                                          int split, float aA[2][4], float aB[2][4],
                                          int bm, int colb, int tid,
                                          const uint32_t* asw, const uint32_t* bsw) {
    int tot = 0;
    for (int i = 0; i < nseg; ++i) tot += segs[i].K >> 6;
    const int npairs = (tot + 1) >> 1;
    Issue st = make_issue(segs, bm, colb, tid);

    const int prefill = npairs < 3 ? npairs : 3;
    for (int pp = 0; pp < prefill; ++pp) {
        issue_next(st, dsm32);
        if (2 * pp + 1 < tot) issue_next(st, dsm32);
        CP_COMMIT();
    }
    for (int p = 0; p < npairs; ++p) {
        const int ahead = npairs - 1 - p;
        if (ahead >= 2)      CP_WAIT2();
        else if (ahead == 1) CP_WAIT1();
        else                 CP_WAIT0();
        __syncthreads();
        if (p + 3 < npairs) {
            issue_next(st, dsm32);
            if (st.c < tot) issue_next(st, dsm32);
            CP_COMMIT();
        }
        const int c0i = 2 * p;
        {
            const uint32_t sb = dsm32 + (c0i & (NSTAGE - 1)) * BUFB;
            compute_chunk(sb, c0i < split ? aA : aB, asw, bsw);
        }
        if (c0i + 1 < tot) {
            const uint32_t sb = dsm32 + ((c0i + 1) & (NSTAGE - 1)) * BUFB;
            compute_chunk(sb, c0i + 1 < split ? aA : aB, asw, bsw);
        }
    }
}

#define ZERO_ACC(A) \
    do { _Pragma("unroll") for (int _a = 0; _a < 2; ++_a) \
         _Pragma("unroll") for (int _d = 0; _d < 4; ++_d) (A)[_a][_d] = 0.0f; } while (0)

// Epilogue: thread owns rows {m, m+8} x ONE unit (all 4 gates).
// acc[0][rr*2+p]: p=0 -> i, p=1 -> f; acc[1][..]: p=0 -> g, p=1 -> o.
__device__ __forceinline__ void epilogue_lstm(float acc[2][4], float* c,
                                              const float* bias,
                                              const float* prevv, const float* Wv,
                                              f16* H,
                                              const float* pjW, float* pacc,
                                              int bm, int G16, int wm, int lane) {
    const int q = lane & 3, r = lane >> 2;
    const float2* b2 = (const float2*)bias;
    const float2 bIF = b2[G16 * 8 + q];
    const float2 bGO = b2[G16 * 8 + 4 + q];
    float2 wIF = make_float2(0.f, 0.f), wGO = make_float2(0.f, 0.f);
    if (Wv) {
        const float2* w2 = (const float2*)Wv;
        wIF = w2[G16 * 8 + q];
        wGO = w2[G16 * 8 + 4 + q];
    }
    const int u = G16 * 4 + q;      // original hidden-unit index
    float pw = 0.0f;
    if (pjW) pw = pjW[u];
    float rsum[2] = {0.0f, 0.0f};
#pragma unroll
    for (int rr = 0; rr < 2; ++rr) {
        const int m = bm + wm * 16 + r + rr * 8;
        float gi = acc[0][rr * 2 + 0] + bIF.x;
        float gf = acc[0][rr * 2 + 1] + bIF.y;
        float gg = acc[1][rr * 2 + 0] + bGO.x;
        float go = acc[1][rr * 2 + 1] + bGO.y;
        if (prevv) {
            const float pv = prevv[m];
            gi = fmaf(pv, wIF.x, gi); gf = fmaf(pv, wIF.y, gf);
            gg = fmaf(pv, wGO.x, gg); go = fmaf(pv, wGO.y, go);
        }
        float cn = sigf(gf) * c[rr] + sigf(gi) * tanhf(gg);
        float hn = sigf(go) * tanhf(cn);
        c[rr] = cn;
        if (pjW) rsum[rr] = hn * pw;
        H[(size_t)m * Hd + u] = __float2half(hn);
    }
    if (pjW) {
#pragma unroll
        for (int rr = 0; rr < 2; ++rr) {
            rsum[rr] += __shfl_xor_sync(0xffffffffu, rsum[rr], 1);
            rsum[rr] += __shfl_xor_sync(0xffffffffu, rsum[rr], 2);
        }
        if (q == 0) {
            atomicAdd(&pacc[bm + wm * 16 + r], rsum[0]);
            atomicAdd(&pacc[bm + wm * 16 + r + 8], rsum[1]);
        }
    }
}

// ------------------------------- prep kernel -------------------------------
// gate g (0..3), unit j (0..511) -> col = 16*(j>>2) + 2*(j&3) + (g&1) + 8*(g>>1)
__device__ __forceinline__ int remap_row(int r) {
    const int g = r >> 9, j = r & 511;
    return ((j >> 2) << 4) + ((j & 3) << 1) + (g & 1) + ((g >> 1) << 3);
}

__global__ void prep_kernel(
    const float* __restrict__ x,
    const float* __restrict__ e0Wih, const float* __restrict__ e0Whh,
    const float* __restrict__ e0bih, const float* __restrict__ e0bhh,
    const float* __restrict__ e1Wih, const float* __restrict__ e1Whh,
    const float* __restrict__ e1bih, const float* __restrict__ e1bhh,
    const float* __restrict__ d0Wih, const float* __restrict__ d0Whh,
    const float* __restrict__ d0bih, const float* __restrict__ d0bhh,
    const float* __restrict__ d1Wih, const float* __restrict__ d1Whh,
    const float* __restrict__ d1bih, const float* __restrict__ d1bhh,
    const float* __restrict__ projb) {
    const size_t FULL = (size_t)N4 * Hd;
    long long idx = (long long)blockIdx.x * 256 + threadIdx.x;

    if (idx < (long long)(6 * FULL)) {
        int seg = (int)(idx / FULL);
        size_t i = (size_t)(idx % FULL);
        int r = (int)(i / Hd), k = (int)(i % Hd);
        size_t dst = (size_t)remap_row(r) * Hd + k;
        const float* src; f16* d;
        switch (seg) {
            case 0: src = e0Whh; d = gB_h0;  break;
            case 1: src = e1Wih; d = gB_x1;  break;
            case 2: src = e1Whh; d = gB_h1;  break;
            case 3: src = d0Whh; d = gB_d0;  break;
            case 4: src = d1Wih; d = gB_x1d; break;
            default: src = d1Whh; d = gB_d1; break;
        }
        d[dst] = __float2half(src[i]);
        return;
    }
    idx -= 6LL * FULL;

    if (idx < (long long)N4 * Fin) {   // Wx0
        size_t i = (size_t)idx;
        int r = (int)(i / Fin), k = (int)(i % Fin);
        gB_x0[(size_t)remap_row(r) * Fin + k] = __float2half(e0Wih[i]);
        return;
    }
    idx -= (long long)N4 * Fin;

    if (idx < (long long)Bsz * T_IN * Fin) {   // x -> [t][b][f]
        size_t i = (size_t)idx;
        int b = (int)(i / (T_IN * Fin));
        int t = (int)((i / Fin) % T_IN);
        int f = (int)(i % Fin);
        g_xc[(size_t)t * Bsz * Fin + b * Fin + f] = __float2half(x[i]);
        return;
    }
    idx -= (long long)Bsz * T_IN * Fin;

    if (idx < N4) {                    // biases + Wv, remapped (fp32)
        int r = (int)idx;
        int dst = remap_row(r);
        g_Wv[dst]  = d0Wih[r];
        g_b0[dst]  = e0bih[r] + e0bhh[r];
        g_b1[dst]  = e1bih[r] + e1bhh[r];
        g_bd0[dst] = d0bih[r] + d0bhh[r];
        g_bd1[dst] = d1bih[r] + d1bhh[r];
        return;
    }
    idx -= N4;

    if (idx < Bsz) {                   // prev slot0 = x[:, -1, -1]; slot1 = projb
        g_pacc[0][idx] = x[(size_t)(idx + 1) * T_IN * Fin - 1];
        g_pacc[1][idx] = projb[0];
        return;
    }
    idx -= Bsz;
    if (idx == 0) g_cnt = 0;
}

// ------------------------------ main kernel --------------------------------
__global__ void __launch_bounds__(THR, 1)
main_kernel(const float* __restrict__ projW,
            const float* __restrict__ projb,
            float* __restrict__ out) {
    extern __shared__ char dsm_raw[];
    const uint32_t raw32 = smem_u32(dsm_raw);
    const uint32_t dsm32 = (raw32 + 1023u) & ~1023u;

    const int tid  = threadIdx.x;
    const int lane = tid & 31;
    const int w    = tid >> 5;         // 0..15
    const int wm   = w & 3;            // M slice (16 rows)
    const int wn   = w >> 2;           // N slice (16 cols)
    const int bid  = blockIdx.x;       // 128 CTAs: 4M x 32N
    const int mT   = bid >> 5;
    const int nT   = bid & 31;
    const int bm   = mT * 64;
    const int colb = nT * 64;
    const int G16  = nT * 4 + wn;      // 16-col block = 4 units x 4 gates

    // Precompute swizzled LDSM offsets (stage-relative); hot loop is IADD-only.
    uint32_t asw[4], bsw[4];
    {
        const int abase = (wm * 16 + (lane & 15)) * 128 + ((lane >> 4) << 4);
        const int bbase = (wn * 16 + (lane & 7) + ((lane >> 4) << 3)) * 128
                        + (((lane >> 3) & 1) << 4);
#pragma unroll
        for (int ka = 0; ka < 4; ++ka) {
            const int ao = abase + ka * 32;
            asw[ka] = ao ^ ((ao >> 3) & 0x70);
            const int bo = bbase + ka * 32;
            bsw[ka] = OFF_B + (bo ^ ((bo >> 3) & 0x70));
        }
    }

    float accA[2][4], accB[2][4];
    float c0[2], c1[2];
    c0[0] = c0[1] = c1[0] = c1[1] = 0.0f;

    Seg segs[4];

    // -------- fused encoder wavefront: superstep s = enc0(s) + enc1(s-1) ----
    for (int s = 0; s <= T_IN; ++s) {
        int ns = 0, split = 0;
        if (s < T_IN) {
            segs[ns++] = { g_xc + (size_t)s * Bsz * Fin, gB_x0, Fin };
            if (s) segs[ns++] = { g_hs + (size_t)(s - 1) * BH, gB_h0, Hd };
            split = s ? 9 : 1;
        }
        if (s >= 1) {
            segs[ns++] = { g_hs + (size_t)(s - 1) * BH, gB_x1, Hd };
            if (s >= 2) segs[ns++] = { &g_h1[s & 1][0], gB_h1, Hd };
        }
        ZERO_ACC(accA); ZERO_ACC(accB);
        pipe_gemm(dsm32, segs, ns, split, accA, accB, bm, colb, tid, asw, bsw);
        if (s < T_IN)
            epilogue_lstm(accA, c0, g_b0, nullptr, nullptr,
                          g_hs + (size_t)s * BH, nullptr, nullptr, bm, G16, wm, lane);
        if (s >= 1)
            epilogue_lstm(accB, c1, g_b1, nullptr, nullptr,
                          &g_h1[(s - 1) & 1][0], nullptr, nullptr, bm, G16, wm, lane);
        grid_sync();
    }

    // -------------------------------- decoder -------------------------------
    const f16 *h0p = g_hs + (size_t)(T_IN - 1) * BH;
    const f16 *h1p = &g_h1[(T_IN - 1) & 1][0];
    const float pjb = projb[0];

    for (int t = 0; t < T_OUT; ++t) {
        // phase A: dec0(t); side tasks: emit out[:,t-1], reseed next slot
        if (bid == 0 && tid < Bsz && t >= 1)
            out[(size_t)tid * T_OUT + (t - 1)] = g_pacc[t & 1][tid];
        if (bid == 1 && tid < Bsz)
            g_pacc[(t + 1) & 1][tid] = pjb;

        segs[0] = { h0p, gB_d0, Hd };
        ZERO_ACC(accA);
        pipe_gemm(dsm32, segs, 1, 8, accA, accA, bm, colb, tid, asw, bsw);
        epilogue_lstm(accA, c0, g_bd0, &g_pacc[t & 1][0], g_Wv,
                      &g_d0[t & 1][0], nullptr, nullptr, bm, G16, wm, lane);
        grid_sync();

        // phase B: dec1(t) + fused projection into pacc[(t+1)&1]
        segs[0] = { &g_d0[t & 1][0], gB_x1d, Hd };
        segs[1] = { h1p, gB_d1, Hd };
        ZERO_ACC(accA);
        pipe_gemm(dsm32, segs, 2, 16, accA, accA, bm, colb, tid, asw, bsw);
        epilogue_lstm(accA, c1, g_bd1, nullptr, nullptr,
                      &g_d1[t & 1][0], projW, &g_pacc[(t + 1) & 1][0],
                      bm, G16, wm, lane);
        grid_sync();

        h0p = &g_d0[t & 1][0];
        h1p = &g_d1[t & 1][0];
    }

    // final output column (t = 63): slot (63+1)&1 = 0
    if (bid == 0 && tid < Bsz)
        out[(size_t)tid * T_OUT + (T_OUT - 1)] = g_pacc[0][tid];
}

// ------------------------------- host side ---------------------------------
extern "C" void kernel_launch(void* const* d_in, const int* in_sizes, int n_in,
                              void* d_out, int out_size) {
    const float* x      = (const float*)d_in[0];
    const float* e0Wih  = (const float*)d_in[2];
    const float* e0Whh  = (const float*)d_in[3];
    const float* e0bih  = (const float*)d_in[4];
    const float* e0bhh  = (const float*)d_in[5];
    const float* e1Wih  = (const float*)d_in[6];
    const float* e1Whh  = (const float*)d_in[7];
    const float* e1bih  = (const float*)d_in[8];
    const float* e1bhh  = (const float*)d_in[9];
    const float* d0Wih  = (const float*)d_in[10];
    const float* d0Whh  = (const float*)d_in[11];
    const float* d0bih  = (const float*)d_in[12];
    const float* d0bhh  = (const float*)d_in[13];
    const float* d1Wih  = (const float*)d_in[14];
    const float* d1Whh  = (const float*)d_in[15];
    const float* d1bih  = (const float*)d_in[16];
    const float* d1bhh  = (const float*)d_in[17];
    const float* projW  = (const float*)d_in[18];
    const float* projb  = (const float*)d_in[19];
    float* out = (float*)d_out;

    const long long total = 6LL * N4 * Hd + (long long)N4 * Fin
                          + (long long)Bsz * T_IN * Fin + N4 + Bsz + 1;
    const int nblk = (int)((total + 255) / 256);
    prep_kernel<<<nblk, 256>>>(x,
        e0Wih, e0Whh, e0bih, e0bhh,
        e1Wih, e1Whh, e1bih, e1bhh,
        d0Wih, d0Whh, d0bih, d0bhh,
        d1Wih, d1Whh, d1bih, d1bhh, projb);

    cudaFuncSetAttribute(main_kernel, cudaFuncAttributeMaxDynamicSharedMemorySize, DSMEM);
    main_kernel<<<NBLK, THR, DSMEM>>>(projW, projb, out);
}

// round 11
// speedup vs baseline: 4.6185x; 1.0748x over previous
#include <cuda_runtime.h>
#include <cuda_fp16.h>
#include <cstdint>
#include <math.h>

// ---------------------------------------------------------------------------
// Seq2Seq LSTM via mma.sync (HMMA fp16): B=256, T_in=512, F=64, H=512, T_out=64
// Round 11: bookkeeping to the floor. Pointer-walking issue cursor (no local-
// memory Seg lookup), QUAD chunk processing on a 12-stage ring (one wait +
// one syncthreads per 4 chunks), running stage bases (no per-chunk IMAD).
// Otherwise round 10: single-pass fp16, 128 CTAs (4M x 32N), 512 thr
// (16 warps, 16x16 tiles), encoder wavefront fusion, fused projection.
// ---------------------------------------------------------------------------

using f16 = __half;

#define Bsz   256
#define Hd    512
#define Fin   64
#define T_IN  512
#define T_OUT 64
#define N4    2048
#define BH    (Bsz*Hd)
#define NBLK  128
#define THR   512

// per-stage smem: A 8K | B 8K
#define OFF_B  8192
#define BUFB   16384
#define NSTAGE 12
#define DSMEM  (NSTAGE*BUFB + 1024)

// ------------------------- device scratch (static) -------------------------
__device__ __align__(16) f16 g_xc[(size_t)T_IN * Bsz * Fin];
__device__ __align__(16) f16 g_hs[(size_t)T_IN * BH];
__device__ __align__(16) f16 g_h1[2][BH];
__device__ __align__(16) f16 g_d0[2][BH];
__device__ __align__(16) f16 g_d1[2][BH];
__device__ float g_pacc[2][Bsz];          // proj ping-pong accumulators

// weights, remapped rows (see remap_row), layout [2048][K] fp16
__device__ __align__(16) f16 gB_x0[N4 * Fin];
__device__ __align__(16) f16 gB_h0[N4 * Hd];
__device__ __align__(16) f16 gB_x1[N4 * Hd];
__device__ __align__(16) f16 gB_h1[N4 * Hd];
__device__ __align__(16) f16 gB_d0[N4 * Hd];
__device__ __align__(16) f16 gB_x1d[N4 * Hd];
__device__ __align__(16) f16 gB_d1[N4 * Hd];

__device__ __align__(16) float g_b0[N4], g_b1[N4], g_bd0[N4], g_bd1[N4], g_Wv[N4];

__device__ unsigned g_cnt;
__device__ volatile unsigned g_gen;

// ------------------------------- asm helpers -------------------------------
#define LDSM4(R, A) \
    asm volatile("ldmatrix.sync.aligned.m8n8.x4.shared.b16 {%0,%1,%2,%3}, [%4];" \
        : "=r"((R)[0]), "=r"((R)[1]), "=r"((R)[2]), "=r"((R)[3]) : "r"(A))

#define MMA(D, A, B) \
    asm volatile("mma.sync.aligned.m16n8k16.row.col.f32.f16.f16.f32 " \
        "{%0,%1,%2,%3}, {%4,%5,%6,%7}, {%8,%9}, {%0,%1,%2,%3};" \
        : "+f"((D)[0]), "+f"((D)[1]), "+f"((D)[2]), "+f"((D)[3]) \
        : "r"((A)[0]), "r"((A)[1]), "r"((A)[2]), "r"((A)[3]), \
          "r"((B)[0]), "r"((B)[1]))

#define CP16(sa, ga) \
    asm volatile("cp.async.cg.shared.global [%0], [%1], 16;" :: "r"(sa), "l"(ga))
#define CP_COMMIT() asm volatile("cp.async.commit_group;")
#define CP_WAIT0()  asm volatile("cp.async.wait_group 0;" ::: "memory")
#define CP_WAIT1()  asm volatile("cp.async.wait_group 1;" ::: "memory")

__device__ __forceinline__ uint32_t smem_u32(const void* p) {
    uint32_t a;
    asm("{ .reg .u64 t; cvta.to.shared.u64 t, %1; cvt.u32.u64 %0, t; }"
        : "=r"(a) : "l"(p));
    return a;
}
__device__ __forceinline__ float sigf(float x) { return 1.0f / (1.0f + expf(-x)); }

__device__ __forceinline__ void grid_sync() {
    __syncthreads();
    if (threadIdx.x == 0) {
        __threadfence();
        unsigned g = g_gen;
        unsigned old = atomicAdd(&g_cnt, 1u);
        if (old == NBLK - 1) {
            g_cnt = 0;
            __threadfence();
            g_gen = g + 1;
        } else {
            while (g_gen == g) __nanosleep(64);
            __threadfence();
        }
    }
    __syncthreads();
}

// ----------------------------- GEMM machinery ------------------------------
struct Seg {
    const f16 *A;   // A [row][K]
    const f16 *B;   // B' [2048][K]
    int K;          // 64 or 512
};

// Warp tile 16x16, single pass fp16; all LDSM offsets precomputed.
__device__ __forceinline__ void compute_chunk(uint32_t sbase, float acc[2][4],
                                              const uint32_t* asw,
                                              const uint32_t* bsw) {
#pragma unroll
    for (int ka = 0; ka < 4; ++ka) {
        uint32_t a[4], b[4];
        LDSM4(a, sbase + asw[ka]);
        LDSM4(b, sbase + bsw[ka]);
        MMA(acc[0], a, b);
        MMA(acc[1], a, b + 2);
    }
}

// 12-stage ring, QUAD groups: one wait + one syncthreads per 4 chunks.
// 3-group rotation: compute g, group g+1 landed, issue group g+2.
__device__ __forceinline__ void pipe_gemm(uint32_t dsm32, const Seg* segs, int nseg,
                                          int split, float aA[2][4], float aB[2][4],
                                          int bm, int colb, int tid,
                                          const uint32_t* asw, const uint32_t* bsw) {
    int tot = 0;
#pragma unroll
    for (int i = 0; i < 4; ++i) if (i < nseg) tot += segs[i].K >> 6;
    const int G = (tot + 3) >> 2;

    const int row = tid >> 3, sg8 = (tid & 7) * 8;
    const uint32_t swA = (uint32_t)((tid * 16) ^ (((tid * 16) >> 3) & 0x70));
    const uint32_t swB = swA + OFF_B;
    const int ra512 = (bm + row) * 512 + sg8;
    const int rb512 = (colb + row) * 512 + sg8;

    // issue cursor: walking pointers, reseed at (rare) segment boundaries
    const f16* pA = segs[0].A + (segs[0].K == 64 ? (bm + row) * 64 + sg8 : ra512);
    const f16* pB = segs[0].B + (segs[0].K == 64 ? (colb + row) * 64 + sg8 : rb512);
    int rem = segs[0].K >> 6;
    int si = 0;
    int issued = 0;
    uint32_t ibase = dsm32;
    const uint32_t wrap = dsm32 + NSTAGE * BUFB;

    auto issue1 = [&]() {
        CP16(ibase + swA, pA);
        CP16(ibase + swB, pB);
        ibase += BUFB;
        if (ibase == wrap) ibase = dsm32;
        ++issued;
        if (--rem == 0) {
            ++si;
            if (si == 1 && nseg > 1) { pA = segs[1].A + ra512; pB = segs[1].B + rb512; rem = segs[1].K >> 6; }
            else if (si == 2 && nseg > 2) { pA = segs[2].A + ra512; pB = segs[2].B + rb512; rem = segs[2].K >> 6; }
            else if (si == 3 && nseg > 3) { pA = segs[3].A + ra512; pB = segs[3].B + rb512; rem = segs[3].K >> 6; }
        } else {
            pA += 64;
            pB += 64;
        }
    };

    // prefill 2 groups
    {
        const int pre = G < 2 ? G : 2;
        for (int g = 0; g < pre; ++g) {
#pragma unroll
            for (int j = 0; j < 4; ++j) if (issued < tot) issue1();
            CP_COMMIT();
        }
    }

    uint32_t cbase = dsm32;
    int c = 0;
    for (int g = 0; g < G; ++g) {
        if (g + 1 < G) CP_WAIT1();
        else           CP_WAIT0();
        __syncthreads();
        if (g + 2 < G) {
#pragma unroll
            for (int j = 0; j < 4; ++j) if (issued < tot) issue1();
            CP_COMMIT();
        }
#pragma unroll
        for (int j = 0; j < 4; ++j) {
            if (c < tot) {
                compute_chunk(cbase, c < split ? aA : aB, asw, bsw);
                cbase += BUFB;
                if (cbase == wrap) cbase = dsm32;
                ++c;
            }
        }
    }
}

#define ZERO_ACC(A) \
    do { _Pragma("unroll") for (int _a = 0; _a < 2; ++_a) \
         _Pragma("unroll") for (int _d = 0; _d < 4; ++_d) (A)[_a][_d] = 0.0f; } while (0)

// Epilogue: thread owns rows {m, m+8} x ONE unit (all 4 gates).
// acc[0][rr*2+p]: p=0 -> i, p=1 -> f; acc[1][..]: p=0 -> g, p=1 -> o.
__device__ __forceinline__ void epilogue_lstm(float acc[2][4], float* c,
                                              const float* bias,
                                              const float* prevv, const float* Wv,
                                              f16* H,
                                              const float* pjW, float* pacc,
                                              int bm, int G16, int wm, int lane) {
    const int q = lane & 3, r = lane >> 2;
    const float2* b2 = (const float2*)bias;
    const float2 bIF = b2[G16 * 8 + q];
    const float2 bGO = b2[G16 * 8 + 4 + q];
    float2 wIF = make_float2(0.f, 0.f), wGO = make_float2(0.f, 0.f);
    if (Wv) {
        const float2* w2 = (const float2*)Wv;
        wIF = w2[G16 * 8 + q];
        wGO = w2[G16 * 8 + 4 + q];
    }
    const int u = G16 * 4 + q;      // original hidden-unit index
    float pw = 0.0f;
    if (pjW) pw = pjW[u];
    float rsum[2] = {0.0f, 0.0f};
#pragma unroll
    for (int rr = 0; rr < 2; ++rr) {
        const int m = bm + wm * 16 + r + rr * 8;
        float gi = acc[0][rr * 2 + 0] + bIF.x;
        float gf = acc[0][rr * 2 + 1] + bIF.y;
        float gg = acc[1][rr * 2 + 0] + bGO.x;
        float go = acc[1][rr * 2 + 1] + bGO.y;
        if (prevv) {
            const float pv = prevv[m];
            gi = fmaf(pv, wIF.x, gi); gf = fmaf(pv, wIF.y, gf);
            gg = fmaf(pv, wGO.x, gg); go = fmaf(pv, wGO.y, go);
        }
        float cn = sigf(gf) * c[rr] + sigf(gi) * tanhf(gg);
        float hn = sigf(go) * tanhf(cn);
        c[rr] = cn;
        if (pjW) rsum[rr] = hn * pw;
        H[(size_t)m * Hd + u] = __float2half(hn);
    }
    if (pjW) {
#pragma unroll
        for (int rr = 0; rr < 2; ++rr) {
            rsum[rr] += __shfl_xor_sync(0xffffffffu, rsum[rr], 1);
            rsum[rr] += __shfl_xor_sync(0xffffffffu, rsum[rr], 2);
        }
        if (q == 0) {
            atomicAdd(&pacc[bm + wm * 16 + r], rsum[0]);
            atomicAdd(&pacc[bm + wm * 16 + r + 8], rsum[1]);
        }
    }
}

// ------------------------------- prep kernel -------------------------------
// gate g (0..3), unit j (0..511) -> col = 16*(j>>2) + 2*(j&3) + (g&1) + 8*(g>>1)
__device__ __forceinline__ int remap_row(int r) {
    const int g = r >> 9, j = r & 511;
    return ((j >> 2) << 4) + ((j & 3) << 1) + (g & 1) + ((g >> 1) << 3);
}

__global__ void prep_kernel(
    const float* __restrict__ x,
    const float* __restrict__ e0Wih, const float* __restrict__ e0Whh,
    const float* __restrict__ e0bih, const float* __restrict__ e0bhh,
    const float* __restrict__ e1Wih, const float* __restrict__ e1Whh,
    const float* __restrict__ e1bih, const float* __restrict__ e1bhh,
    const float* __restrict__ d0Wih, const float* __restrict__ d0Whh,
    const float* __restrict__ d0bih, const float* __restrict__ d0bhh,
    const float* __restrict__ d1Wih, const float* __restrict__ d1Whh,
    const float* __restrict__ d1bih, const float* __restrict__ d1bhh,
    const float* __restrict__ projb) {
    const size_t FULL = (size_t)N4 * Hd;
    long long idx = (long long)blockIdx.x * 256 + threadIdx.x;

    if (idx < (long long)(6 * FULL)) {
        int seg = (int)(idx / FULL);
        size_t i = (size_t)(idx % FULL);
        int r = (int)(i / Hd), k = (int)(i % Hd);
        size_t dst = (size_t)remap_row(r) * Hd + k;
        const float* src; f16* d;
        switch (seg) {
            case 0: src = e0Whh; d = gB_h0;  break;
            case 1: src = e1Wih; d = gB_x1;  break;
            case 2: src = e1Whh; d = gB_h1;  break;
            case 3: src = d0Whh; d = gB_d0;  break;
            case 4: src = d1Wih; d = gB_x1d; break;
            default: src = d1Whh; d = gB_d1; break;
        }
        d[dst] = __float2half(src[i]);
        return;
    }
    idx -= 6LL * FULL;

    if (idx < (long long)N4 * Fin) {   // Wx0
        size_t i = (size_t)idx;
        int r = (int)(i / Fin), k = (int)(i % Fin);
        gB_x0[(size_t)remap_row(r) * Fin + k] = __float2half(e0Wih[i]);
        return;
    }
    idx -= (long long)N4 * Fin;

    if (idx < (long long)Bsz * T_IN * Fin) {   // x -> [t][b][f]
        size_t i = (size_t)idx;
        int b = (int)(i / (T_IN * Fin));
        int t = (int)((i / Fin) % T_IN);
        int f = (int)(i % Fin);
        g_xc[(size_t)t * Bsz * Fin + b * Fin + f] = __float2half(x[i]);
        return;
    }
    idx -= (long long)Bsz * T_IN * Fin;

    if (idx < N4) {                    // biases + Wv, remapped (fp32)
        int r = (int)idx;
        int dst = remap_row(r);
        g_Wv[dst]  = d0Wih[r];
        g_b0[dst]  = e0bih[r] + e0bhh[r];
        g_b1[dst]  = e1bih[r] + e1bhh[r];
        g_bd0[dst] = d0bih[r] + d0bhh[r];
        g_bd1[dst] = d1bih[r] + d1bhh[r];
        return;
    }
    idx -= N4;

    if (idx < Bsz) {                   // prev slot0 = x[:, -1, -1]; slot1 = projb
        g_pacc[0][idx] = x[(size_t)(idx + 1) * T_IN * Fin - 1];
        g_pacc[1][idx] = projb[0];
        return;
    }
    idx -= Bsz;
    if (idx == 0) g_cnt = 0;
}

// ------------------------------ main kernel --------------------------------
__global__ void __launch_bounds__(THR, 1)
main_kernel(const float* __restrict__ projW,
            const float* __restrict__ projb,
            float* __restrict__ out) {
    extern __shared__ char dsm_raw[];
    const uint32_t raw32 = smem_u32(dsm_raw);
    const uint32_t dsm32 = (raw32 + 1023u) & ~1023u;

    const int tid  = threadIdx.x;
    const int lane = tid & 31;
    const int w    = tid >> 5;         // 0..15
    const int wm   = w & 3;            // M slice (16 rows)
    const int wn   = w >> 2;           // N slice (16 cols)
    const int bid  = blockIdx.x;       // 128 CTAs: 4M x 32N
    const int mT   = bid >> 5;
    const int nT   = bid & 31;
    const int bm   = mT * 64;
    const int colb = nT * 64;
    const int G16  = nT * 4 + wn;      // 16-col block = 4 units x 4 gates

    // Precompute swizzled LDSM offsets (stage-relative); hot loop is IADD-only.
    uint32_t asw[4], bsw[4];
    {
        const int abase = (wm * 16 + (lane & 15)) * 128 + ((lane >> 4) << 4);
        const int bbase = (wn * 16 + (lane & 7) + ((lane >> 4) << 3)) * 128
                        + (((lane >> 3) & 1) << 4);
#pragma unroll
        for (int ka = 0; ka < 4; ++ka) {
            const int ao = abase + ka * 32;
            asw[ka] = ao ^ ((ao >> 3) & 0x70);
            const int bo = bbase + ka * 32;
            bsw[ka] = OFF_B + (bo ^ ((bo >> 3) & 0x70));
        }
    }

    float accA[2][4], accB[2][4];
    float c0[2], c1[2];
    c0[0] = c0[1] = c1[0] = c1[1] = 0.0f;

    Seg segs[4];

    // -------- fused encoder wavefront: superstep s = enc0(s) + enc1(s-1) ----
    for (int s = 0; s <= T_IN; ++s) {
        int ns = 0, split = 0;
        if (s < T_IN) {
            segs[ns++] = { g_xc + (size_t)s * Bsz * Fin, gB_x0, Fin };
            if (s) segs[ns++] = { g_hs + (size_t)(s - 1) * BH, gB_h0, Hd };
            split = s ? 9 : 1;
        }
        if (s >= 1) {
            segs[ns++] = { g_hs + (size_t)(s - 1) * BH, gB_x1, Hd };
            if (s >= 2) segs[ns++] = { &g_h1[s & 1][0], gB_h1, Hd };
        }
        ZERO_ACC(accA); ZERO_ACC(accB);
        pipe_gemm(dsm32, segs, ns, split, accA, accB, bm, colb, tid, asw, bsw);
        if (s < T_IN)
            epilogue_lstm(accA, c0, g_b0, nullptr, nullptr,
                          g_hs + (size_t)s * BH, nullptr, nullptr, bm, G16, wm, lane);
        if (s >= 1)
            epilogue_lstm(accB, c1, g_b1, nullptr, nullptr,
                          &g_h1[(s - 1) & 1][0], nullptr, nullptr, bm, G16, wm, lane);
        grid_sync();
    }

    // -------------------------------- decoder -------------------------------
    const f16 *h0p = g_hs + (size_t)(T_IN - 1) * BH;
    const f16 *h1p = &g_h1[(T_IN - 1) & 1][0];
    const float pjb = projb[0];

    for (int t = 0; t < T_OUT; ++t) {
        // phase A: dec0(t); side tasks: emit out[:,t-1], reseed next slot
        if (bid == 0 && tid < Bsz && t >= 1)
            out[(size_t)tid * T_OUT + (t - 1)] = g_pacc[t & 1][tid];
        if (bid == 1 && tid < Bsz)
            g_pacc[(t + 1) & 1][tid] = pjb;

        segs[0] = { h0p, gB_d0, Hd };
        ZERO_ACC(accA);
        pipe_gemm(dsm32, segs, 1, 8, accA, accA, bm, colb, tid, asw, bsw);
        epilogue_lstm(accA, c0, g_bd0, &g_pacc[t & 1][0], g_Wv,
                      &g_d0[t & 1][0], nullptr, nullptr, bm, G16, wm, lane);
        grid_sync();

        // phase B: dec1(t) + fused projection into pacc[(t+1)&1]
        segs[0] = { &g_d0[t & 1][0], gB_x1d, Hd };
        segs[1] = { h1p, gB_d1, Hd };
        ZERO_ACC(accA);
        pipe_gemm(dsm32, segs, 2, 16, accA, accA, bm, colb, tid, asw, bsw);
        epilogue_lstm(accA, c1, g_bd1, nullptr, nullptr,
                      &g_d1[t & 1][0], projW, &g_pacc[(t + 1) & 1][0],
                      bm, G16, wm, lane);
        grid_sync();

        h0p = &g_d0[t & 1][0];
        h1p = &g_d1[t & 1][0];
    }

    // final output column (t = 63): slot (63+1)&1 = 0
    if (bid == 0 && tid < Bsz)
        out[(size_t)tid * T_OUT + (T_OUT - 1)] = g_pacc[0][tid];
}

// ------------------------------- host side ---------------------------------
extern "C" void kernel_launch(void* const* d_in, const int* in_sizes, int n_in,
                              void* d_out, int out_size) {
    const float* x      = (const float*)d_in[0];
    const float* e0Wih  = (const float*)d_in[2];
    const float* e0Whh  = (const float*)d_in[3];
    const float* e0bih  = (const float*)d_in[4];
    const float* e0bhh  = (const float*)d_in[5];
    const float* e1Wih  = (const float*)d_in[6];
    const float* e1Whh  = (const float*)d_in[7];
    const float* e1bih  = (const float*)d_in[8];
    const float* e1bhh  = (const float*)d_in[9];
    const float* d0Wih  = (const float*)d_in[10];
    const float* d0Whh  = (const float*)d_in[11];
    const float* d0bih  = (const float*)d_in[12];
    const float* d0bhh  = (const float*)d_in[13];
    const float* d1Wih  = (const float*)d_in[14];
    const float* d1Whh  = (const float*)d_in[15];
    const float* d1bih  = (const float*)d_in[16];
    const float* d1bhh  = (const float*)d_in[17];
    const float* projW  = (const float*)d_in[18];
    const float* projb  = (const float*)d_in[19];
    float* out = (float*)d_out;

    const long long total = 6LL * N4 * Hd + (long long)N4 * Fin
                          + (long long)Bsz * T_IN * Fin + N4 + Bsz + 1;
    const int nblk = (int)((total + 255) / 256);
    prep_kernel<<<nblk, 256>>>(x,
        e0Wih, e0Whh, e0bih, e0bhh,
        e1Wih, e1Whh, e1bih, e1bhh,
        d0Wih, d0Whh, d0bih, d0bhh,
        d1Wih, d1Whh, d1bih, d1bhh, projb);

    cudaFuncSetAttribute(main_kernel, cudaFuncAttributeMaxDynamicSharedMemorySize, DSMEM);
    main_kernel<<<NBLK, THR, DSMEM>>>(projW, projb, out);
}